// round 15
// baseline (speedup 1.0000x reference)
#include <cuda_runtime.h>
#include <cuda_bf16.h>
#include <cuda_fp16.h>
#include <math.h>
#include <stdint.h>

#define NN 10000
#define EMAX 400000

// ------------------------- scratch (static device globals) -------------------------
__device__ int   g_flag64;
__device__ int   g_src[EMAX];
__device__ int   g_dstA[EMAX];
__device__ int   g_cnt[NN];
__device__ int   g_rowptr[NN + 1];
__device__ int   g_cursor[NN];
__device__ int   g_csr[EMAX];
__device__ __half g_Hh[NN * 512];    // x @ W_gat, fp16
__device__ float g_as[NN * 2];
__device__ float g_ad[NN * 2];
__device__ float g_vas[512 * 2];
__device__ float g_vad[512 * 2];
__device__ float g_pre[NN * 256];    // pre-LN buffer (layerA)
__device__ float4 g_h4[NN];
__device__ float2 g_w2[EMAX];
__device__ float  g_zi[NN * 2];
__device__ __nv_bfloat16 g_Bhi[512 * 512];    // W_gat^T hi (bf16x3 path)
__device__ __nv_bfloat16 g_Blo[512 * 512];    // W_gat^T lo
__device__ __half g_BhA16[256 * 512];         // Wa^T fp16 hi
__device__ __half g_BlA16[256 * 512];         // Wa^T fp16 lo (residual)
__device__ __half g_BhW116[128 * 256];        // W1^T fp16 hi
__device__ __half g_BlW116[128 * 256];        // W1^T fp16 lo
__device__ __nv_bfloat16 g_Xhi[NN * 512];     // x hi (bf16, gemm1 A)
__device__ __nv_bfloat16 g_Xlo[NN * 512];     // x lo
__device__ __half g_Xh16[NN * 512];           // fp16 activations (gat acts, then layerA out)

// ------------------------- helpers -------------------------
__device__ __forceinline__ uint32_t smem_u32(const void* p) {
    uint32_t a;
    asm("{ .reg .u64 t; cvta.to.shared.u64 t, %1; cvt.u32.u64 %0, t; }" : "=r"(a) : "l"(p));
    return a;
}
__device__ __forceinline__ void cp16(const void* smem_dst, const void* gsrc) {
    uint32_t s = smem_u32(smem_dst);
    asm volatile("cp.async.cg.shared.global [%0], [%1], 16;" :: "r"(s), "l"(gsrc));
}
#define CP_COMMIT() asm volatile("cp.async.commit_group;" ::: "memory")
#define CP_WAIT0()  asm volatile("cp.async.wait_group 0;" ::: "memory")
#define CP_WAIT1()  asm volatile("cp.async.wait_group 1;" ::: "memory")

__device__ __forceinline__ void mma_bf16(float* c, const uint32_t* a, const uint32_t* b) {
    asm volatile(
        "mma.sync.aligned.m16n8k16.row.col.f32.bf16.bf16.f32 "
        "{%0,%1,%2,%3}, {%4,%5,%6,%7}, {%8,%9}, {%0,%1,%2,%3};"
        : "+f"(c[0]), "+f"(c[1]), "+f"(c[2]), "+f"(c[3])
        : "r"(a[0]), "r"(a[1]), "r"(a[2]), "r"(a[3]), "r"(b[0]), "r"(b[1]));
}
__device__ __forceinline__ void mma_f16(float* c, const uint32_t* a, const uint32_t* b) {
    asm volatile(
        "mma.sync.aligned.m16n8k16.row.col.f32.f16.f16.f32 "
        "{%0,%1,%2,%3}, {%4,%5,%6,%7}, {%8,%9}, {%0,%1,%2,%3};"
        : "+f"(c[0]), "+f"(c[1]), "+f"(c[2]), "+f"(c[3])
        : "r"(a[0]), "r"(a[1]), "r"(a[2]), "r"(a[3]), "r"(b[0]), "r"(b[1]));
}
__device__ __forceinline__ uint32_t pack_bf2(float a, float b) {
    __nv_bfloat162 t = __floats2bfloat162_rn(a, b);
    return *(uint32_t*)&t;
}
__device__ __forceinline__ float fsqrt_ap(float x) {
    float y;
    asm("sqrt.approx.f32 %0, %1;" : "=f"(y) : "f"(x));
    return y;
}

// ------------------------- edge dtype detect + convert -------------------------
__global__ void k_detect(const void* ei) {
    const long long* p = (const long long*)ei;
    int ok = 1;
    for (int i = 0; i < 8; i++) {
        long long v = p[i];
        if (v < 0 || v >= NN) ok = 0;
    }
    g_flag64 = ok;
}

__global__ void k_convert(const void* ei, int E) {
    int i = blockIdx.x * blockDim.x + threadIdx.x;
    int tot = E + NN;
    if (i >= tot || i >= EMAX) return;
    int s, d;
    if (i < E) {
        if (g_flag64) {
            const long long* p = (const long long*)ei;
            s = (int)p[i];
            d = (int)p[E + i];
        } else {
            const int* p = (const int*)ei;
            s = p[i];
            d = p[E + i];
        }
    } else {
        s = d = i - E;
    }
    g_src[i] = s;
    g_dstA[i] = d;
    atomicAdd(&g_cnt[d], 1);
}

// fast single-block exclusive scan
__global__ void k_scan() {
    __shared__ int wsum[32];
    int tid = threadIdx.x;
    int lane = tid & 31, warp = tid >> 5;
    int base = tid * 10;
    int v[10];
    int s = 0;
#pragma unroll
    for (int j = 0; j < 10; j++) {
        int idx = base + j;
        v[j] = (idx < NN) ? g_cnt[idx] : 0;
        s += v[j];
    }
    int x = s;
#pragma unroll
    for (int off = 1; off < 32; off <<= 1) {
        int t = __shfl_up_sync(0xffffffffu, x, off);
        if (lane >= off) x += t;
    }
    if (lane == 31) wsum[warp] = x;
    __syncthreads();
    if (warp == 0) {
        int y = wsum[lane];
#pragma unroll
        for (int off = 1; off < 32; off <<= 1) {
            int t = __shfl_up_sync(0xffffffffu, y, off);
            if (lane >= off) y += t;
        }
        wsum[lane] = y;
    }
    __syncthreads();
    int excl = x - s + (warp ? wsum[warp - 1] : 0);
    int run = excl;
#pragma unroll
    for (int j = 0; j < 10; j++) {
        int idx = base + j;
        if (idx < NN) {
            g_rowptr[idx] = run;
            g_cursor[idx] = run;
            run += v[j];
        }
    }
    if (tid == 1023) g_rowptr[NN] = run;
}

__global__ void k_scatter(int tot) {
    int i = blockIdx.x * blockDim.x + threadIdx.x;
    if (i >= tot || i >= EMAX) return;
    int d = g_dstA[i];
    int pos = atomicAdd(&g_cursor[d], 1);
    g_csr[pos] = g_src[i];
}

// ------------------------- fp32 -> bf16 hi/lo split (x for gemm1) -------------------------
__global__ void k_split(const float4* __restrict__ X, uint2* __restrict__ hi,
                        uint2* __restrict__ lo, int n4) {
    int i = blockIdx.x * blockDim.x + threadIdx.x;
    if (i >= n4) return;
    float4 v = X[i];
    __nv_bfloat16 h0 = __float2bfloat16_rn(v.x), h1 = __float2bfloat16_rn(v.y);
    __nv_bfloat16 h2 = __float2bfloat16_rn(v.z), h3 = __float2bfloat16_rn(v.w);
    float l0 = v.x - __bfloat162float(h0), l1 = v.y - __bfloat162float(h1);
    float l2 = v.z - __bfloat162float(h2), l3 = v.w - __bfloat162float(h3);
    uint32_t hp0 = (((uint32_t)*(uint16_t*)&h1) << 16) | (uint32_t)*(uint16_t*)&h0;
    uint32_t hp1 = (((uint32_t)*(uint16_t*)&h3) << 16) | (uint32_t)*(uint16_t*)&h2;
    hi[i] = make_uint2(hp0, hp1);
    lo[i] = make_uint2(pack_bf2(l0, l1), pack_bf2(l2, l3));
}

// W [K][N] -> B^T bf16 hi/lo [n][k]
__global__ void k_prepWT(const float* __restrict__ W, int K, int N,
                         __nv_bfloat16* __restrict__ Bh, __nv_bfloat16* __restrict__ Bl) {
    int n = blockIdx.x;
    for (int k = threadIdx.x; k < K; k += blockDim.x) {
        float v = W[(size_t)k * N + n];
        __nv_bfloat16 h = __float2bfloat16_rn(v);
        float r = v - __bfloat162float(h);
        Bh[(size_t)n * K + k] = h;
        Bl[(size_t)n * K + k] = __float2bfloat16_rn(r);
    }
}

// W [K][N] -> B^T fp16 hi/lo [n][k]
__global__ void k_prepWT16(const float* __restrict__ W, int K, int N,
                           __half* __restrict__ Bh, __half* __restrict__ Bl) {
    int n = blockIdx.x;
    for (int k = threadIdx.x; k < K; k += blockDim.x) {
        float v = W[(size_t)k * N + n];
        __half h = __float2half_rn(v);
        float r = v - __half2float(h);
        Bh[(size_t)n * K + k] = h;
        Bl[(size_t)n * K + k] = __float2half_rn(r);
    }
}

// ------------------------- attention vectors: va = W_gat @ att (per head) -------------------------
__global__ void k_attvec(const float* __restrict__ W, const float* __restrict__ attS,
                         const float* __restrict__ attD) {
    int idx = (blockIdx.x * blockDim.x + threadIdx.x) >> 5;
    int lane = threadIdx.x & 31;
    if (idx >= 1024) return;
    int k = idx >> 1, h = idx & 1;
    const float* wrow = W + (size_t)k * 512 + h * 256;
    const float* as = attS + h * 256;
    const float* ad = attD + h * 256;
    float s = 0.f, d = 0.f;
#pragma unroll
    for (int j = 0; j < 8; j++) {
        int c = lane + j * 32;
        float w = wrow[c];
        s = fmaf(w, __ldg(&as[c]), s);
        d = fmaf(w, __ldg(&ad[c]), d);
    }
#pragma unroll
    for (int off = 16; off; off >>= 1) {
        s += __shfl_xor_sync(0xffffffffu, s, off);
        d += __shfl_xor_sync(0xffffffffu, d, off);
    }
    if (lane == 0) {
        g_vas[k * 2 + h] = s;
        g_vad[k * 2 + h] = d;
    }
}

// ------------------------- attention dots from x directly -------------------------
__global__ void k_attdot2(const float* __restrict__ x) {
    int node = (blockIdx.x * blockDim.x + threadIdx.x) >> 5;
    int lane = threadIdx.x & 31;
    if (node >= NN) return;
    const float* xr = x + (size_t)node * 512;
    float s0 = 0.f, s1 = 0.f, d0 = 0.f, d1 = 0.f;
#pragma unroll
    for (int j = 0; j < 16; j++) {
        int k = lane + j * 32;
        float xv = xr[k];
        s0 = fmaf(xv, g_vas[k * 2], s0);
        s1 = fmaf(xv, g_vas[k * 2 + 1], s1);
        d0 = fmaf(xv, g_vad[k * 2], d0);
        d1 = fmaf(xv, g_vad[k * 2 + 1], d1);
    }
#pragma unroll
    for (int off = 16; off; off >>= 1) {
        s0 += __shfl_xor_sync(0xffffffffu, s0, off);
        s1 += __shfl_xor_sync(0xffffffffu, s1, off);
        d0 += __shfl_xor_sync(0xffffffffu, d0, off);
        d1 += __shfl_xor_sync(0xffffffffu, d1, off);
    }
    if (lane == 0) {
        g_as[node * 2] = s0;
        g_as[node * 2 + 1] = s1;
        g_ad[node * 2] = d0;
        g_ad[node * 2 + 1] = d1;
    }
}

// ------------------------- GEMM via mma.sync -------------------------
// AF16 == 0: bf16x3 (A hi/lo + B hi/lo, 3 mma per tile pair)
// AF16 == 1: fp16 2-term (A single fp16, B fp16 hi/lo, 2 mma), 3-tile stages (2 CTAs/SM)
// EPI 0: plain fp32 store.
// EPI 1: full fused tail (NTOT==128): bias+LN(128)+tanh(relu) -> layer2 + LN(64)+relu -> layer3 -> g_h4
// EPI 3: fp16 store to g_Hh (ldc = NTOT)
#define GTILE 18432                 // one 128x(64+8pad) 16-bit tile
#define GLDS 144                    // bytes per smem row (72 elems)

template <int KTOT, int NTOT, int EPI, int AF16>
__global__ __launch_bounds__(256) void k_gemm_mma(
    const __nv_bfloat16* __restrict__ Ah, const __nv_bfloat16* __restrict__ Al,
    const __nv_bfloat16* __restrict__ Bh, const __nv_bfloat16* __restrict__ Bl,
    float* __restrict__ C, int M,
    const float* __restrict__ lnb, const float* __restrict__ lng,
    const float* __restrict__ lnbt,
    const float* __restrict__ W2p, const float* __restrict__ b2p,
    const float* __restrict__ g2p, const float* __restrict__ bn2p,
    const float* __restrict__ W3p, const float* __restrict__ b3p) {
    constexpr int STAGES = KTOT / 64;
    constexpr int BH_OFF = (AF16 ? 1 : 2) * GTILE;
    constexpr int BL_OFF = BH_OFF + GTILE;
    constexpr int GSTAGE = (AF16 ? 3 : 4) * GTILE;
    extern __shared__ char sm[];
    const int tid = threadIdx.x;
    const int wid = tid >> 5, lane = tid & 31;
    const int g = lane >> 2, tg = lane & 3;
    const int warpM = wid & 3, warpN = wid >> 2;
    const int mBase = blockIdx.y * 128;
    const int nBase = blockIdx.x * 128;

    float acc[2][8][4];
#pragma unroll
    for (int a = 0; a < 2; a++)
#pragma unroll
        for (int b = 0; b < 8; b++)
#pragma unroll
            for (int c = 0; c < 4; c++) acc[a][b][c] = 0.f;

    auto load_stage = [&](int buf, int k0) {
        char* st = sm + buf * GSTAGE;
#pragma unroll
        for (int t = 0; t < 4; t++) {
            int idx = tid + t * 256;
            int row = idx >> 3, seg = idx & 7;
            int gr = mBase + row;
            if (gr > M - 1) gr = M - 1;
            size_t ga = (size_t)gr * KTOT + k0 + seg * 8;
            size_t gb = (size_t)(nBase + row) * KTOT + k0 + seg * 8;
            uint32_t so = row * GLDS + seg * 16;
            cp16(st + so, Ah + ga);
            if (!AF16) cp16(st + GTILE + so, Al + ga);
            cp16(st + BH_OFF + so, Bh + gb);
            cp16(st + BL_OFF + so, Bl + gb);
        }
    };

    load_stage(0, 0);
    CP_COMMIT();

    for (int s = 0; s < STAGES; s++) {
        if (s + 1 < STAGES) {
            load_stage((s + 1) & 1, (s + 1) * 64);
            CP_COMMIT();
            CP_WAIT1();
        } else {
            CP_WAIT0();
        }
        __syncthreads();
        const char* st = sm + (s & 1) * GSTAGE;
#pragma unroll
        for (int ks = 0; ks < 4; ks++) {
            int k2 = ks * 16 + tg * 2;
            uint32_t ah[2][4], al[2][4];
#pragma unroll
            for (int ms = 0; ms < 2; ms++) {
                int r0 = warpM * 32 + ms * 16 + g;
                const char* pa = st + r0 * GLDS + k2 * 2;
                ah[ms][0] = *(const uint32_t*)(pa);
                ah[ms][1] = *(const uint32_t*)(pa + 8 * GLDS);
                ah[ms][2] = *(const uint32_t*)(pa + 16);
                ah[ms][3] = *(const uint32_t*)(pa + 8 * GLDS + 16);
                if (!AF16) {
                    const char* pl = pa + GTILE;
                    al[ms][0] = *(const uint32_t*)(pl);
                    al[ms][1] = *(const uint32_t*)(pl + 8 * GLDS);
                    al[ms][2] = *(const uint32_t*)(pl + 16);
                    al[ms][3] = *(const uint32_t*)(pl + 8 * GLDS + 16);
                }
            }
            uint32_t bh[8][2], bl[8][2];
#pragma unroll
            for (int ns = 0; ns < 8; ns++) {
                int r = warpN * 64 + ns * 8 + g;
                const char* pb = st + BH_OFF + r * GLDS + k2 * 2;
                bh[ns][0] = *(const uint32_t*)(pb);
                bh[ns][1] = *(const uint32_t*)(pb + 16);
                bl[ns][0] = *(const uint32_t*)(pb + GTILE);
                bl[ns][1] = *(const uint32_t*)(pb + GTILE + 16);
            }
#pragma unroll
            for (int ms = 0; ms < 2; ms++)
#pragma unroll
                for (int ns = 0; ns < 8; ns++) {
                    if (AF16) {
                        mma_f16(acc[ms][ns], ah[ms], bh[ns]);
                        mma_f16(acc[ms][ns], ah[ms], bl[ns]);
                    } else {
                        mma_bf16(acc[ms][ns], ah[ms], bh[ns]);
                        mma_bf16(acc[ms][ns], ah[ms], bl[ns]);
                        mma_bf16(acc[ms][ns], al[ms], bh[ns]);
                    }
                }
        }
        __syncthreads();
    }

    if (EPI == 0) {
#pragma unroll
        for (int ms = 0; ms < 2; ms++) {
            int row = mBase + warpM * 32 + ms * 16 + g;
#pragma unroll
            for (int ns = 0; ns < 8; ns++) {
                int col = nBase + warpN * 64 + ns * 8 + tg * 2;
                if (col >= NTOT) continue;
                if (row < M)
                    *(float2*)&C[(size_t)row * NTOT + col] =
                        make_float2(acc[ms][ns][0], acc[ms][ns][1]);
                if (row + 8 < M)
                    *(float2*)&C[(size_t)(row + 8) * NTOT + col] =
                        make_float2(acc[ms][ns][2], acc[ms][ns][3]);
            }
        }
    } else if (EPI == 3) {
        // fp16 store into g_Hh
#pragma unroll
        for (int ms = 0; ms < 2; ms++) {
            int row = mBase + warpM * 32 + ms * 16 + g;
#pragma unroll
            for (int ns = 0; ns < 8; ns++) {
                int col = nBase + warpN * 64 + ns * 8 + tg * 2;
                if (row < M) {
                    __half2 p = __floats2half2_rn(acc[ms][ns][0], acc[ms][ns][1]);
                    *(__half2*)&g_Hh[(size_t)row * NTOT + col] = p;
                }
                if (row + 8 < M) {
                    __half2 p = __floats2half2_rn(acc[ms][ns][2], acc[ms][ns][3]);
                    *(__half2*)&g_Hh[(size_t)(row + 8) * NTOT + col] = p;
                }
            }
        }
    } else {
        // ---- full fused tail: LN(128)+tanh(relu) -> layer2 -> LN(64)+relu -> layer3 -> g_h4
        float* Ys  = (float*)sm;               // 128 x 128 fp32 (64 KB)
        float* W2s = (float*)(sm + 65536);     // 128 x 64 fp32 (32 KB)
        __shared__ float W3s[192];
        __shared__ float b3s[3];

#pragma unroll
        for (int ms = 0; ms < 2; ms++) {
            int r = warpM * 32 + ms * 16 + g;
#pragma unroll
            for (int ns = 0; ns < 8; ns++) {
                int c = warpN * 64 + ns * 8 + tg * 2;
                Ys[r * 128 + c] = acc[ms][ns][0];
                Ys[r * 128 + c + 1] = acc[ms][ns][1];
                Ys[(r + 8) * 128 + c] = acc[ms][ns][2];
                Ys[(r + 8) * 128 + c + 1] = acc[ms][ns][3];
            }
        }
        for (int i = tid; i < 128 * 64; i += 256) W2s[i] = W2p[i];
        if (tid < 192) W3s[tid] = W3p[tid];
        if (tid < 3) b3s[tid] = b3p[tid];
        __syncthreads();

        for (int rr = 0; rr < 16; rr++) {
            int r = wid * 16 + rr;
            float v[4];
            float s = 0.f, s2 = 0.f;
#pragma unroll
            for (int j = 0; j < 4; j++) {
                int c = lane + j * 32;
                v[j] = Ys[r * 128 + c] + lnb[c];
                s += v[j];
                s2 = fmaf(v[j], v[j], s2);
            }
#pragma unroll
            for (int off = 16; off; off >>= 1) {
                s  += __shfl_xor_sync(0xffffffffu, s, off);
                s2 += __shfl_xor_sync(0xffffffffu, s2, off);
            }
            float mu = s * (1.f / 128.f);
            float var = s2 * (1.f / 128.f) - mu * mu;
            float rs = rsqrtf(fmaxf(var, 0.f) + 1e-5f);
#pragma unroll
            for (int j = 0; j < 4; j++) {
                int c = lane + j * 32;
                float o = (v[j] - mu) * rs * lng[c] + lnbt[c];
                Ys[r * 128 + c] = o > 0.f ? tanhf(o) : 0.f;
            }
        }
        __syncthreads();

        float acc2[16][2];
        {
            float bb0 = __ldg(&b2p[2 * lane]), bb1 = __ldg(&b2p[2 * lane + 1]);
#pragma unroll
            for (int j = 0; j < 16; j++) { acc2[j][0] = bb0; acc2[j][1] = bb1; }
        }
        for (int k4 = 0; k4 < 32; k4++) {
            float2 w[4];
#pragma unroll
            for (int q = 0; q < 4; q++)
                w[q] = *(const float2*)&W2s[(k4 * 4 + q) * 64 + 2 * lane];
#pragma unroll
            for (int j = 0; j < 16; j++) {
                float4 xv = *(const float4*)&Ys[(wid * 16 + j) * 128 + k4 * 4];
                acc2[j][0] = fmaf(xv.x, w[0].x, acc2[j][0]);
                acc2[j][1] = fmaf(xv.x, w[0].y, acc2[j][1]);
                acc2[j][0] = fmaf(xv.y, w[1].x, acc2[j][0]);
                acc2[j][1] = fmaf(xv.y, w[1].y, acc2[j][1]);
                acc2[j][0] = fmaf(xv.z, w[2].x, acc2[j][0]);
                acc2[j][1] = fmaf(xv.z, w[2].y, acc2[j][1]);
                acc2[j][0] = fmaf(xv.w, w[3].x, acc2[j][0]);
                acc2[j][1] = fmaf(xv.w, w[3].y, acc2[j][1]);
            }
        }

        float gg0 = __ldg(&g2p[2 * lane]), gg1 = __ldg(&g2p[2 * lane + 1]);
        float bt0 = __ldg(&bn2p[2 * lane]), bt1 = __ldg(&bn2p[2 * lane + 1]);
        float w30a = W3s[(2 * lane) * 3 + 0], w31a = W3s[(2 * lane) * 3 + 1],
              w32a = W3s[(2 * lane) * 3 + 2];
        float w30b = W3s[(2 * lane + 1) * 3 + 0], w31b = W3s[(2 * lane + 1) * 3 + 1],
              w32b = W3s[(2 * lane + 1) * 3 + 2];
        for (int j = 0; j < 16; j++) {
            float a = acc2[j][0], b = acc2[j][1];
            float s = a + b;
            float s2 = fmaf(a, a, b * b);
#pragma unroll
            for (int off = 16; off; off >>= 1) {
                s  += __shfl_xor_sync(0xffffffffu, s, off);
                s2 += __shfl_xor_sync(0xffffffffu, s2, off);
            }
            float mu = s * (1.f / 64.f);
            float var = s2 * (1.f / 64.f) - mu * mu;
            float rs = rsqrtf(fmaxf(var, 0.f) + 1e-5f);
            float va = (a - mu) * rs * gg0 + bt0;
            float vb = (b - mu) * rs * gg1 + bt1;
            va = va > 0.f ? va : 0.f;
            vb = vb > 0.f ? vb : 0.f;
            float o0 = fmaf(va, w30a, vb * w30b);
            float o1 = fmaf(va, w31a, vb * w31b);
            float o2 = fmaf(va, w32a, vb * w32b);
#pragma unroll
            for (int off = 16; off; off >>= 1) {
                o0 += __shfl_down_sync(0xffffffffu, o0, off);
                o1 += __shfl_down_sync(0xffffffffu, o1, off);
                o2 += __shfl_down_sync(0xffffffffu, o2, off);
            }
            int grow = mBase + wid * 16 + j;
            if (lane == 0 && grow < M) {
                o0 += b3s[0];
                o1 += b3s[1];
                o2 += b3s[2];
                float sq = o0 * o0 + o1 * o1 + o2 * o2;
                g_h4[grow] = make_float4(o0, o1, o2, sq);
            }
        }
    }
}

// ------------------------- per-edge softmax weights (one warp per dst) -------------------------
__device__ __forceinline__ float lrelu02(float x) { return x > 0.f ? x : 0.2f * x; }

__global__ void k_alpha() {
    int gw = (blockIdx.x * blockDim.x + threadIdx.x) >> 5;
    int lane = threadIdx.x & 31;
    if (gw >= NN) return;
    int s0 = g_rowptr[gw], s1 = g_rowptr[gw + 1];
    float ad0 = g_ad[gw * 2], ad1 = g_ad[gw * 2 + 1];
    float m0 = -1e30f, m1 = -1e30f;
    for (int i = s0 + lane; i < s1; i += 32) {
        int s = g_csr[i];
        m0 = fmaxf(m0, lrelu02(g_as[s * 2] + ad0));
        m1 = fmaxf(m1, lrelu02(g_as[s * 2 + 1] + ad1));
    }
#pragma unroll
    for (int off = 16; off; off >>= 1) {
        m0 = fmaxf(m0, __shfl_xor_sync(0xffffffffu, m0, off));
        m1 = fmaxf(m1, __shfl_xor_sync(0xffffffffu, m1, off));
    }
    float z0 = 0.f, z1 = 0.f;
    for (int i = s0 + lane; i < s1; i += 32) {
        int s = g_csr[i];
        float w0 = __expf(lrelu02(g_as[s * 2] + ad0) - m0);
        float w1 = __expf(lrelu02(g_as[s * 2 + 1] + ad1) - m1);
        g_w2[i] = make_float2(w0, w1);
        z0 += w0;
        z1 += w1;
    }
#pragma unroll
    for (int off = 16; off; off >>= 1) {
        z0 += __shfl_xor_sync(0xffffffffu, z0, off);
        z1 += __shfl_xor_sync(0xffffffffu, z1, off);
    }
    if (lane == 0) {
        g_zi[gw * 2]     = 1.f / (z0 + 1e-16f);
        g_zi[gw * 2 + 1] = 1.f / (z1 + 1e-16f);
    }
}

// ------------------------- aggregate (fp16 gather) + relu + fp16 out -------------------------
__global__ void k_agg2(const float* __restrict__ bgat) {
    int n = blockIdx.x;
    int t = threadIdx.x;  // 128 threads, 4 channels each
    int head = t >> 6;
    int s0 = g_rowptr[n], s1 = g_rowptr[n + 1];
    float4 acc = make_float4(0.f, 0.f, 0.f, 0.f);
    int i = s0;
    for (; i + 4 <= s1; i += 4) {
        int sa = g_csr[i], sb = g_csr[i + 1], sc = g_csr[i + 2], sd = g_csr[i + 3];
        float2 wa2 = g_w2[i], wb2 = g_w2[i + 1], wc2 = g_w2[i + 2], wd2 = g_w2[i + 3];
        float wa = head ? wa2.y : wa2.x;
        float wb = head ? wb2.y : wb2.x;
        float wc = head ? wc2.y : wc2.x;
        float wd = head ? wd2.y : wd2.x;
        uint2 ua = *(const uint2*)&g_Hh[(size_t)sa * 512 + t * 4];
        uint2 ub = *(const uint2*)&g_Hh[(size_t)sb * 512 + t * 4];
        uint2 uc = *(const uint2*)&g_Hh[(size_t)sc * 512 + t * 4];
        uint2 ud = *(const uint2*)&g_Hh[(size_t)sd * 512 + t * 4];
        float2 a01 = __half22float2(*(__half2*)&ua.x), a23 = __half22float2(*(__half2*)&ua.y);
        float2 b01 = __half22float2(*(__half2*)&ub.x), b23 = __half22float2(*(__half2*)&ub.y);
        float2 c01 = __half22float2(*(__half2*)&uc.x), c23 = __half22float2(*(__half2*)&uc.y);
        float2 d01 = __half22float2(*(__half2*)&ud.x), d23 = __half22float2(*(__half2*)&ud.y);
        acc.x = fmaf(wa, a01.x, fmaf(wb, b01.x, fmaf(wc, c01.x, fmaf(wd, d01.x, acc.x))));
        acc.y = fmaf(wa, a01.y, fmaf(wb, b01.y, fmaf(wc, c01.y, fmaf(wd, d01.y, acc.y))));
        acc.z = fmaf(wa, a23.x, fmaf(wb, b23.x, fmaf(wc, c23.x, fmaf(wd, d23.x, acc.z))));
        acc.w = fmaf(wa, a23.y, fmaf(wb, b23.y, fmaf(wc, c23.y, fmaf(wd, d23.y, acc.w))));
    }
    for (; i < s1; i++) {
        int s = g_csr[i];
        float2 w2 = g_w2[i];
        float w = head ? w2.y : w2.x;
        uint2 u = *(const uint2*)&g_Hh[(size_t)s * 512 + t * 4];
        float2 h01 = __half22float2(*(__half2*)&u.x), h23 = __half22float2(*(__half2*)&u.y);
        acc.x = fmaf(w, h01.x, acc.x);
        acc.y = fmaf(w, h01.y, acc.y);
        acc.z = fmaf(w, h23.x, acc.z);
        acc.w = fmaf(w, h23.y, acc.w);
    }
    float zi = g_zi[n * 2 + head];
    float4 b4 = *(const float4*)&bgat[t * 4];
    float4 o;
    o.x = fmaf(acc.x, zi, b4.x);
    o.y = fmaf(acc.y, zi, b4.y);
    o.z = fmaf(acc.z, zi, b4.z);
    o.w = fmaf(acc.w, zi, b4.w);
    o.x = o.x > 0.f ? o.x : 0.f;
    o.y = o.y > 0.f ? o.y : 0.f;
    o.z = o.z > 0.f ? o.z : 0.f;
    o.w = o.w > 0.f ? o.w : 0.f;
    __half2 p01 = __floats2half2_rn(o.x, o.y);
    __half2 p23 = __floats2half2_rn(o.z, o.w);
    ((uint2*)g_Xh16)[(size_t)n * 128 + t] =
        make_uint2(*(uint32_t*)&p01, *(uint32_t*)&p23);
}

// ------------------------- bias + LN + relu epilogue, fp16 out (layerA) -------------------------
__global__ void k_ln_act256(const float* __restrict__ pre, const float* __restrict__ bias,
                            const float* __restrict__ gam, const float* __restrict__ bet,
                            __half* __restrict__ o16) {
    int row = blockIdx.x * 8 + (threadIdx.x >> 5);
    int lane = threadIdx.x & 31;
    if (row >= NN) return;
    const float* p = pre + (size_t)row * 256;
    float v[8];
    float s = 0.f, s2 = 0.f;
#pragma unroll
    for (int j = 0; j < 8; j++) {
        int c = lane + j * 32;
        v[j] = p[c] + bias[c];
        s += v[j];
        s2 = fmaf(v[j], v[j], s2);
    }
#pragma unroll
    for (int off = 16; off; off >>= 1) {
        s  += __shfl_xor_sync(0xffffffffu, s, off);
        s2 += __shfl_xor_sync(0xffffffffu, s2, off);
    }
    float mu = s * (1.f / 256.f);
    float var = s2 * (1.f / 256.f) - mu * mu;
    float rs = rsqrtf(fmaxf(var, 0.f) + 1e-5f);
#pragma unroll
    for (int j = 0; j < 8; j++) {
        int c = lane + j * 32;
        float o = (v[j] - mu) * rs * gam[c] + bet[c];
        o = o > 0.f ? o : 0.f;
        o16[(size_t)row * 256 + c] = __float2half_rn(o);
    }
}

// ------------------------- pairwise distance (MUFU.SQRT, streaming stores) -------------------------
__device__ __forceinline__ float pdist(float4 a, float4 b) {
    float dot = fmaf(a.x, b.x, fmaf(a.y, b.y, a.z * b.z));
    float d = fmaf(-2.f, dot, a.w + b.w);
    return fsqrt_ap(fmaxf(d, 0.f));
}

__global__ void k_cdist(float* __restrict__ out) {
    int j4 = blockIdx.x * blockDim.x + threadIdx.x;
    if (j4 >= NN / 4) return;
    int i0 = blockIdx.y * 4;
    float4 bq0 = g_h4[4 * j4 + 0];
    float4 bq1 = g_h4[4 * j4 + 1];
    float4 bq2 = g_h4[4 * j4 + 2];
    float4 bq3 = g_h4[4 * j4 + 3];
#pragma unroll
    for (int r = 0; r < 4; r++) {
        float4 a = g_h4[i0 + r];
        float4 o = make_float4(pdist(a, bq0), pdist(a, bq1), pdist(a, bq2), pdist(a, bq3));
        __stcs((float4*)(out + (size_t)(i0 + r) * NN + 4 * j4), o);
    }
}

// ------------------------- streams -------------------------
static cudaStream_t s_edge = nullptr, s_wts = nullptr;
static cudaEvent_t ev_start = nullptr, ev_edge = nullptr, ev_wts = nullptr, ev_wts2 = nullptr;
struct HxInit {
    HxInit() {
        cudaStreamCreateWithFlags(&s_edge, cudaStreamNonBlocking);
        cudaStreamCreateWithFlags(&s_wts, cudaStreamNonBlocking);
        cudaEventCreateWithFlags(&ev_start, cudaEventDisableTiming);
        cudaEventCreateWithFlags(&ev_edge, cudaEventDisableTiming);
        cudaEventCreateWithFlags(&ev_wts, cudaEventDisableTiming);
        cudaEventCreateWithFlags(&ev_wts2, cudaEventDisableTiming);
    }
};
static HxInit g_hxinit;

// ------------------------- launch -------------------------
extern "C" void kernel_launch(void* const* d_in, const int* in_sizes, int n_in,
                              void* d_out, int out_size) {
    const float* x      = (const float*)d_in[0];
    const void*  ei     = d_in[1];
    const float* W_gat  = (const float*)d_in[2];
    const float* attS   = (const float*)d_in[3];
    const float* attD   = (const float*)d_in[4];
    const float* b_gat  = (const float*)d_in[5];
    const float* Wa     = (const float*)d_in[6];
    const float* ba     = (const float*)d_in[7];
    const float* ga     = (const float*)d_in[8];
    const float* bna    = (const float*)d_in[9];
    const float* W1     = (const float*)d_in[10];
    const float* b1     = (const float*)d_in[11];
    const float* g1     = (const float*)d_in[12];
    const float* bn1    = (const float*)d_in[13];
    const float* W2     = (const float*)d_in[14];
    const float* b2     = (const float*)d_in[15];
    const float* g2     = (const float*)d_in[16];
    const float* bn2    = (const float*)d_in[17];
    const float* W3     = (const float*)d_in[18];
    const float* b3     = (const float*)d_in[19];
    float* out = (float*)d_out;

    int E = in_sizes[1] / 2;
    int tot = E + NN;

    static float* pPre = nullptr;
    static int* pCnt = nullptr;
    static __nv_bfloat16 *pBhi = nullptr, *pBlo = nullptr, *pXhi = nullptr, *pXlo = nullptr;
    static __half *pBhA = nullptr, *pBlA = nullptr, *pBhW1 = nullptr, *pBlW1 = nullptr,
                  *pX16 = nullptr;
    static bool attrDone = false;
    if (!pPre) {
        cudaGetSymbolAddress((void**)&pPre, g_pre);
        cudaGetSymbolAddress((void**)&pCnt, g_cnt);
        cudaGetSymbolAddress((void**)&pBhi, g_Bhi);
        cudaGetSymbolAddress((void**)&pBlo, g_Blo);
        cudaGetSymbolAddress((void**)&pBhA, g_BhA16);
        cudaGetSymbolAddress((void**)&pBlA, g_BlA16);
        cudaGetSymbolAddress((void**)&pBhW1, g_BhW116);
        cudaGetSymbolAddress((void**)&pBlW1, g_BlW116);
        cudaGetSymbolAddress((void**)&pXhi, g_Xhi);
        cudaGetSymbolAddress((void**)&pXlo, g_Xlo);
        cudaGetSymbolAddress((void**)&pX16, g_Xh16);
    }
    if (!attrDone) {
        cudaFuncSetAttribute((const void*)k_gemm_mma<512, 512, 3, 0>,
                             cudaFuncAttributeMaxDynamicSharedMemorySize, 2 * 4 * GTILE);
        cudaFuncSetAttribute((const void*)k_gemm_mma<512, 256, 0, 1>,
                             cudaFuncAttributeMaxDynamicSharedMemorySize, 2 * 3 * GTILE);
        cudaFuncSetAttribute((const void*)k_gemm_mma<256, 128, 1, 1>,
                             cudaFuncAttributeMaxDynamicSharedMemorySize, 2 * 3 * GTILE);
        attrDone = true;
    }

    // fork
    cudaEventRecord(ev_start, 0);
    cudaStreamWaitEvent(s_edge, ev_start, 0);
    cudaStreamWaitEvent(s_wts, ev_start, 0);

    // edge + attention-weight chain (stream E)
    cudaMemsetAsync(pCnt, 0, NN * sizeof(int), s_edge);
    k_detect<<<1, 1, 0, s_edge>>>(ei);
    k_convert<<<(tot + 255) / 256, 256, 0, s_edge>>>(ei, E);
    k_scan<<<1, 1024, 0, s_edge>>>();
    k_scatter<<<(tot + 255) / 256, 256, 0, s_edge>>>(tot);
    k_attvec<<<128, 256, 0, s_edge>>>(W_gat, attS, attD);
    k_attdot2<<<(NN * 32 + 255) / 256, 256, 0, s_edge>>>(x);
    k_alpha<<<(NN * 32 + 255) / 256, 256, 0, s_edge>>>();
    cudaEventRecord(ev_edge, s_edge);

    // weight splits (stream W)
    k_prepWT<<<512, 256, 0, s_wts>>>(W_gat, 512, 512, pBhi, pBlo);
    cudaEventRecord(ev_wts, s_wts);
    k_prepWT16<<<256, 256, 0, s_wts>>>(Wa, 512, 256, pBhA, pBlA);
    k_prepWT16<<<128, 256, 0, s_wts>>>(W1, 256, 128, pBhW1, pBlW1);
    cudaEventRecord(ev_wts2, s_wts);

    // main pipeline (origin stream)
    int n4x = NN * 512 / 4;
    k_split<<<(n4x + 255) / 256, 256>>>((const float4*)x, (uint2*)pXhi, (uint2*)pXlo, n4x);
    cudaStreamWaitEvent(0, ev_wts, 0);
    {
        dim3 gg(4, (NN + 127) / 128);
        k_gemm_mma<512, 512, 3, 0><<<gg, 256, 2 * 4 * GTILE>>>(
            pXhi, pXlo, pBhi, pBlo, nullptr, NN, nullptr, nullptr, nullptr,
            nullptr, nullptr, nullptr, nullptr, nullptr, nullptr);
    }

    cudaStreamWaitEvent(0, ev_edge, 0);
    k_agg2<<<NN, 128>>>(b_gat);   // fp16 gather; emits fp16 acts into g_Xh16

    cudaStreamWaitEvent(0, ev_wts2, 0);
    // layer A (fp16 2-term): pre = gat @ Wa  -> LN+relu -> fp16
    {
        dim3 gg(2, (NN + 127) / 128);
        k_gemm_mma<512, 256, 0, 1><<<gg, 256, 2 * 3 * GTILE>>>(
            (const __nv_bfloat16*)pX16, nullptr,
            (const __nv_bfloat16*)pBhA, (const __nv_bfloat16*)pBlA,
            pPre, NN, nullptr, nullptr, nullptr,
            nullptr, nullptr, nullptr, nullptr, nullptr, nullptr);
    }
    k_ln_act256<<<(NN + 7) / 8, 256>>>(pPre, ba, ga, bna, pX16);

    // layer 1 (fp16 2-term) with fully fused tail -> g_h4
    {
        dim3 gg(1, (NN + 127) / 128);
        k_gemm_mma<256, 128, 1, 1><<<gg, 256, 2 * 3 * GTILE>>>(
            (const __nv_bfloat16*)pX16, nullptr,
            (const __nv_bfloat16*)pBhW1, (const __nv_bfloat16*)pBlW1,
            nullptr, NN, b1, g1, bn1,
            W2, b2, g2, bn2, W3, b3);
    }

    dim3 gc((NN / 4 + 255) / 256, NN / 4);
    k_cdist<<<gc, 256>>>(out);
}

// round 16
// speedup vs baseline: 1.5035x; 1.5035x over previous
#include <cuda_runtime.h>
#include <cuda_bf16.h>
#include <cuda_fp16.h>
#include <math.h>
#include <stdint.h>

#define NN 10000
#define EMAX 400000

// ------------------------- scratch (static device globals) -------------------------
__device__ int   g_flag64;
__device__ int   g_src[EMAX];
__device__ int   g_dstA[EMAX];
__device__ int   g_cnt[NN];
__device__ int   g_rowptr[NN + 1];
__device__ int   g_cursor[NN];
__device__ int   g_csr[EMAX];
__device__ __half g_Hh[NN * 512];    // x @ W_gat, fp16 (halves agg gather traffic)
__device__ float g_as[NN * 2];
__device__ float g_ad[NN * 2];
__device__ float g_vas[512 * 2];     // W_gat @ att_src  [k][h]
__device__ float g_vad[512 * 2];     // W_gat @ att_dst  [k][h]
__device__ float g_pre[NN * 256];    // pre-LN buffer (layerA)
__device__ float4 g_h4[NN];
__device__ float2 g_w2[EMAX];
__device__ float  g_zi[NN * 2];
__device__ __nv_bfloat16 g_Bhi[512 * 512];    // W_gat^T hi  [n][k]
__device__ __nv_bfloat16 g_Blo[512 * 512];    // W_gat^T lo
__device__ __nv_bfloat16 g_Bhi2[256 * 512];   // Wa^T hi
__device__ __nv_bfloat16 g_Blo2[256 * 512];   // Wa^T lo
__device__ __nv_bfloat16 g_BhiW1[128 * 256];  // W1^T hi
__device__ __nv_bfloat16 g_BloW1[128 * 256];  // W1^T lo
__device__ __nv_bfloat16 g_Xhi[NN * 512];     // activations hi [m][k]
__device__ __nv_bfloat16 g_Xlo[NN * 512];     // activations lo

// ------------------------- helpers -------------------------
__device__ __forceinline__ uint32_t smem_u32(const void* p) {
    uint32_t a;
    asm("{ .reg .u64 t; cvta.to.shared.u64 t, %1; cvt.u32.u64 %0, t; }" : "=r"(a) : "l"(p));
    return a;
}
__device__ __forceinline__ void cp16(const void* smem_dst, const void* gsrc) {
    uint32_t s = smem_u32(smem_dst);
    asm volatile("cp.async.cg.shared.global [%0], [%1], 16;" :: "r"(s), "l"(gsrc));
}
#define CP_COMMIT() asm volatile("cp.async.commit_group;" ::: "memory")
#define CP_WAIT0()  asm volatile("cp.async.wait_group 0;" ::: "memory")
#define CP_WAIT1()  asm volatile("cp.async.wait_group 1;" ::: "memory")

__device__ __forceinline__ void mma_bf16(float* c, const uint32_t* a, const uint32_t* b) {
    asm volatile(
        "mma.sync.aligned.m16n8k16.row.col.f32.bf16.bf16.f32 "
        "{%0,%1,%2,%3}, {%4,%5,%6,%7}, {%8,%9}, {%0,%1,%2,%3};"
        : "+f"(c[0]), "+f"(c[1]), "+f"(c[2]), "+f"(c[3])
        : "r"(a[0]), "r"(a[1]), "r"(a[2]), "r"(a[3]), "r"(b[0]), "r"(b[1]));
}
__device__ __forceinline__ uint32_t pack_bf2(float a, float b) {
    __nv_bfloat162 t = __floats2bfloat162_rn(a, b);
    return *(uint32_t*)&t;
}
__device__ __forceinline__ float fsqrt_ap(float x) {
    float y;
    asm("sqrt.approx.f32 %0, %1;" : "=f"(y) : "f"(x));
    return y;
}

// ------------------------- edge dtype detect + convert -------------------------
__global__ void k_detect(const void* ei) {
    const long long* p = (const long long*)ei;
    int ok = 1;
    for (int i = 0; i < 8; i++) {
        long long v = p[i];
        if (v < 0 || v >= NN) ok = 0;
    }
    g_flag64 = ok;
}

__global__ void k_convert(const void* ei, int E) {
    int i = blockIdx.x * blockDim.x + threadIdx.x;
    int tot = E + NN;
    if (i >= tot || i >= EMAX) return;
    int s, d;
    if (i < E) {
        if (g_flag64) {
            const long long* p = (const long long*)ei;
            s = (int)p[i];
            d = (int)p[E + i];
        } else {
            const int* p = (const int*)ei;
            s = p[i];
            d = p[E + i];
        }
    } else {
        s = d = i - E;
    }
    g_src[i] = s;
    g_dstA[i] = d;
    atomicAdd(&g_cnt[d], 1);
}

// fast single-block exclusive scan
__global__ void k_scan() {
    __shared__ int wsum[32];
    int tid = threadIdx.x;
    int lane = tid & 31, warp = tid >> 5;
    int base = tid * 10;
    int v[10];
    int s = 0;
#pragma unroll
    for (int j = 0; j < 10; j++) {
        int idx = base + j;
        v[j] = (idx < NN) ? g_cnt[idx] : 0;
        s += v[j];
    }
    int x = s;
#pragma unroll
    for (int off = 1; off < 32; off <<= 1) {
        int t = __shfl_up_sync(0xffffffffu, x, off);
        if (lane >= off) x += t;
    }
    if (lane == 31) wsum[warp] = x;
    __syncthreads();
    if (warp == 0) {
        int y = wsum[lane];
#pragma unroll
        for (int off = 1; off < 32; off <<= 1) {
            int t = __shfl_up_sync(0xffffffffu, y, off);
            if (lane >= off) y += t;
        }
        wsum[lane] = y;
    }
    __syncthreads();
    int excl = x - s + (warp ? wsum[warp - 1] : 0);
    int run = excl;
#pragma unroll
    for (int j = 0; j < 10; j++) {
        int idx = base + j;
        if (idx < NN) {
            g_rowptr[idx] = run;
            g_cursor[idx] = run;
            run += v[j];
        }
    }
    if (tid == 1023) g_rowptr[NN] = run;
}

__global__ void k_scatter(int tot) {
    int i = blockIdx.x * blockDim.x + threadIdx.x;
    if (i >= tot || i >= EMAX) return;
    int d = g_dstA[i];
    int pos = atomicAdd(&g_cursor[d], 1);
    g_csr[pos] = g_src[i];
}

// ------------------------- fp32 -> bf16 hi/lo split -------------------------
__global__ void k_split(const float4* __restrict__ X, uint2* __restrict__ hi,
                        uint2* __restrict__ lo, int n4) {
    int i = blockIdx.x * blockDim.x + threadIdx.x;
    if (i >= n4) return;
    float4 v = X[i];
    __nv_bfloat16 h0 = __float2bfloat16_rn(v.x), h1 = __float2bfloat16_rn(v.y);
    __nv_bfloat16 h2 = __float2bfloat16_rn(v.z), h3 = __float2bfloat16_rn(v.w);
    float l0 = v.x - __bfloat162float(h0), l1 = v.y - __bfloat162float(h1);
    float l2 = v.z - __bfloat162float(h2), l3 = v.w - __bfloat162float(h3);
    uint32_t hp0 = (((uint32_t)*(uint16_t*)&h1) << 16) | (uint32_t)*(uint16_t*)&h0;
    uint32_t hp1 = (((uint32_t)*(uint16_t*)&h3) << 16) | (uint32_t)*(uint16_t*)&h2;
    hi[i] = make_uint2(hp0, hp1);
    lo[i] = make_uint2(pack_bf2(l0, l1), pack_bf2(l2, l3));
}

// W [K][N] -> B^T hi/lo [n][k]
__global__ void k_prepWT(const float* __restrict__ W, int K, int N,
                         __nv_bfloat16* __restrict__ Bh, __nv_bfloat16* __restrict__ Bl) {
    int n = blockIdx.x;
    for (int k = threadIdx.x; k < K; k += blockDim.x) {
        float v = W[(size_t)k * N + n];
        __nv_bfloat16 h = __float2bfloat16_rn(v);
        float r = v - __bfloat162float(h);
        Bh[(size_t)n * K + k] = h;
        Bl[(size_t)n * K + k] = __float2bfloat16_rn(r);
    }
}

// ------------------------- attention vectors: va = W_gat @ att (per head) -------------------------
__global__ void k_attvec(const float* __restrict__ W, const float* __restrict__ attS,
                         const float* __restrict__ attD) {
    int idx = (blockIdx.x * blockDim.x + threadIdx.x) >> 5;
    int lane = threadIdx.x & 31;
    if (idx >= 1024) return;
    int k = idx >> 1, h = idx & 1;
    const float* wrow = W + (size_t)k * 512 + h * 256;
    const float* as = attS + h * 256;
    const float* ad = attD + h * 256;
    float s = 0.f, d = 0.f;
#pragma unroll
    for (int j = 0; j < 8; j++) {
        int c = lane + j * 32;
        float w = wrow[c];
        s = fmaf(w, __ldg(&as[c]), s);
        d = fmaf(w, __ldg(&ad[c]), d);
    }
#pragma unroll
    for (int off = 16; off; off >>= 1) {
        s += __shfl_xor_sync(0xffffffffu, s, off);
        d += __shfl_xor_sync(0xffffffffu, d, off);
    }
    if (lane == 0) {
        g_vas[k * 2 + h] = s;
        g_vad[k * 2 + h] = d;
    }
}

// ------------------------- attention dots from x directly -------------------------
__global__ void k_attdot2(const float* __restrict__ x) {
    int node = (blockIdx.x * blockDim.x + threadIdx.x) >> 5;
    int lane = threadIdx.x & 31;
    if (node >= NN) return;
    const float* xr = x + (size_t)node * 512;
    float s0 = 0.f, s1 = 0.f, d0 = 0.f, d1 = 0.f;
#pragma unroll
    for (int j = 0; j < 16; j++) {
        int k = lane + j * 32;
        float xv = xr[k];
        s0 = fmaf(xv, g_vas[k * 2], s0);
        s1 = fmaf(xv, g_vas[k * 2 + 1], s1);
        d0 = fmaf(xv, g_vad[k * 2], d0);
        d1 = fmaf(xv, g_vad[k * 2 + 1], d1);
    }
#pragma unroll
    for (int off = 16; off; off >>= 1) {
        s0 += __shfl_xor_sync(0xffffffffu, s0, off);
        s1 += __shfl_xor_sync(0xffffffffu, s1, off);
        d0 += __shfl_xor_sync(0xffffffffu, d0, off);
        d1 += __shfl_xor_sync(0xffffffffu, d1, off);
    }
    if (lane == 0) {
        g_as[node * 2] = s0;
        g_as[node * 2 + 1] = s1;
        g_ad[node * 2] = d0;
        g_ad[node * 2 + 1] = d1;
    }
}

// ------------------------- bf16x3 GEMM via mma.sync -------------------------
// EPI 0: plain fp32 store.
// EPI 1: full fused tail (NTOT==128): bias+LN(128)+tanh(relu) -> layer2 + LN(64)+relu -> layer3 -> g_h4
// EPI 3: fp16 store to g_Hh (ldc = NTOT)
#define GTILE 18432                 // one 128x(64+8pad) bf16 tile
#define GSTAGE (4 * GTILE)
#define GLDS 144                    // bytes per smem row (72 bf16)

template <int KTOT, int NTOT, int EPI>
__global__ __launch_bounds__(256) void k_gemm_mma(
    const __nv_bfloat16* __restrict__ Ah, const __nv_bfloat16* __restrict__ Al,
    const __nv_bfloat16* __restrict__ Bh, const __nv_bfloat16* __restrict__ Bl,
    float* __restrict__ C, int M,
    const float* __restrict__ lnb, const float* __restrict__ lng,
    const float* __restrict__ lnbt,
    const float* __restrict__ W2p, const float* __restrict__ b2p,
    const float* __restrict__ g2p, const float* __restrict__ bn2p,
    const float* __restrict__ W3p, const float* __restrict__ b3p) {
    constexpr int STAGES = KTOT / 64;
    extern __shared__ char sm[];
    const int tid = threadIdx.x;
    const int wid = tid >> 5, lane = tid & 31;
    const int g = lane >> 2, tg = lane & 3;
    const int warpM = wid & 3, warpN = wid >> 2;
    const int mBase = blockIdx.y * 128;
    const int nBase = blockIdx.x * 128;

    float acc[2][8][4];
#pragma unroll
    for (int a = 0; a < 2; a++)
#pragma unroll
        for (int b = 0; b < 8; b++)
#pragma unroll
            for (int c = 0; c < 4; c++) acc[a][b][c] = 0.f;

    auto load_stage = [&](int buf, int k0) {
        char* st = sm + buf * GSTAGE;
#pragma unroll
        for (int t = 0; t < 4; t++) {
            int idx = tid + t * 256;
            int row = idx >> 3, seg = idx & 7;
            int gr = mBase + row;
            if (gr > M - 1) gr = M - 1;
            size_t ga = (size_t)gr * KTOT + k0 + seg * 8;
            size_t gb = (size_t)(nBase + row) * KTOT + k0 + seg * 8;
            uint32_t so = row * GLDS + seg * 16;
            cp16(st + so, Ah + ga);
            cp16(st + GTILE + so, Al + ga);
            cp16(st + 2 * GTILE + so, Bh + gb);
            cp16(st + 3 * GTILE + so, Bl + gb);
        }
    };

    load_stage(0, 0);
    CP_COMMIT();

    for (int s = 0; s < STAGES; s++) {
        if (s + 1 < STAGES) {
            load_stage((s + 1) & 1, (s + 1) * 64);
            CP_COMMIT();
            CP_WAIT1();
        } else {
            CP_WAIT0();
        }
        __syncthreads();
        const char* st = sm + (s & 1) * GSTAGE;
#pragma unroll
        for (int ks = 0; ks < 4; ks++) {
            int k2 = ks * 16 + tg * 2;
            uint32_t ah[2][4], al[2][4];
#pragma unroll
            for (int ms = 0; ms < 2; ms++) {
                int r0 = warpM * 32 + ms * 16 + g;
                const char* pa = st + r0 * GLDS + k2 * 2;
                ah[ms][0] = *(const uint32_t*)(pa);
                ah[ms][1] = *(const uint32_t*)(pa + 8 * GLDS);
                ah[ms][2] = *(const uint32_t*)(pa + 16);
                ah[ms][3] = *(const uint32_t*)(pa + 8 * GLDS + 16);
                const char* pl = pa + GTILE;
                al[ms][0] = *(const uint32_t*)(pl);
                al[ms][1] = *(const uint32_t*)(pl + 8 * GLDS);
                al[ms][2] = *(const uint32_t*)(pl + 16);
                al[ms][3] = *(const uint32_t*)(pl + 8 * GLDS + 16);
            }
            uint32_t bh[8][2], bl[8][2];
#pragma unroll
            for (int ns = 0; ns < 8; ns++) {
                int r = warpN * 64 + ns * 8 + g;
                const char* pb = st + 2 * GTILE + r * GLDS + k2 * 2;
                bh[ns][0] = *(const uint32_t*)(pb);
                bh[ns][1] = *(const uint32_t*)(pb + 16);
                bl[ns][0] = *(const uint32_t*)(pb + GTILE);
                bl[ns][1] = *(const uint32_t*)(pb + GTILE + 16);
            }
#pragma unroll
            for (int ms = 0; ms < 2; ms++)
#pragma unroll
                for (int ns = 0; ns < 8; ns++) {
                    mma_bf16(acc[ms][ns], ah[ms], bh[ns]);
                    mma_bf16(acc[ms][ns], ah[ms], bl[ns]);
                    mma_bf16(acc[ms][ns], al[ms], bh[ns]);
                }
        }
        __syncthreads();
    }

    if (EPI == 0) {
#pragma unroll
        for (int ms = 0; ms < 2; ms++) {
            int row = mBase + warpM * 32 + ms * 16 + g;
#pragma unroll
            for (int ns = 0; ns < 8; ns++) {
                int col = nBase + warpN * 64 + ns * 8 + tg * 2;
                if (col >= NTOT) continue;
                if (row < M)
                    *(float2*)&C[(size_t)row * NTOT + col] =
                        make_float2(acc[ms][ns][0], acc[ms][ns][1]);
                if (row + 8 < M)
                    *(float2*)&C[(size_t)(row + 8) * NTOT + col] =
                        make_float2(acc[ms][ns][2], acc[ms][ns][3]);
            }
        }
    } else if (EPI == 3) {
        // fp16 store into g_Hh
#pragma unroll
        for (int ms = 0; ms < 2; ms++) {
            int row = mBase + warpM * 32 + ms * 16 + g;
#pragma unroll
            for (int ns = 0; ns < 8; ns++) {
                int col = nBase + warpN * 64 + ns * 8 + tg * 2;
                if (row < M) {
                    __half2 p = __floats2half2_rn(acc[ms][ns][0], acc[ms][ns][1]);
                    *(__half2*)&g_Hh[(size_t)row * NTOT + col] = p;
                }
                if (row + 8 < M) {
                    __half2 p = __floats2half2_rn(acc[ms][ns][2], acc[ms][ns][3]);
                    *(__half2*)&g_Hh[(size_t)(row + 8) * NTOT + col] = p;
                }
            }
        }
    } else {
        // ---- full fused tail: LN(128)+tanh(relu) -> layer2 -> LN(64)+relu -> layer3 -> g_h4
        float* Ys  = (float*)sm;               // 128 x 128 fp32 (64 KB)
        float* W2s = (float*)(sm + 65536);     // 128 x 64 fp32 (32 KB)
        __shared__ float W3s[192];
        __shared__ float b3s[3];

#pragma unroll
        for (int ms = 0; ms < 2; ms++) {
            int r = warpM * 32 + ms * 16 + g;
#pragma unroll
            for (int ns = 0; ns < 8; ns++) {
                int c = warpN * 64 + ns * 8 + tg * 2;
                Ys[r * 128 + c] = acc[ms][ns][0];
                Ys[r * 128 + c + 1] = acc[ms][ns][1];
                Ys[(r + 8) * 128 + c] = acc[ms][ns][2];
                Ys[(r + 8) * 128 + c + 1] = acc[ms][ns][3];
            }
        }
        for (int i = tid; i < 128 * 64; i += 256) W2s[i] = W2p[i];
        if (tid < 192) W3s[tid] = W3p[tid];
        if (tid < 3) b3s[tid] = b3p[tid];
        __syncthreads();

        for (int rr = 0; rr < 16; rr++) {
            int r = wid * 16 + rr;
            float v[4];
            float s = 0.f, s2 = 0.f;
#pragma unroll
            for (int j = 0; j < 4; j++) {
                int c = lane + j * 32;
                v[j] = Ys[r * 128 + c] + lnb[c];
                s += v[j];
                s2 = fmaf(v[j], v[j], s2);
            }
#pragma unroll
            for (int off = 16; off; off >>= 1) {
                s  += __shfl_xor_sync(0xffffffffu, s, off);
                s2 += __shfl_xor_sync(0xffffffffu, s2, off);
            }
            float mu = s * (1.f / 128.f);
            float var = s2 * (1.f / 128.f) - mu * mu;
            float rs = rsqrtf(fmaxf(var, 0.f) + 1e-5f);
#pragma unroll
            for (int j = 0; j < 4; j++) {
                int c = lane + j * 32;
                float o = (v[j] - mu) * rs * lng[c] + lnbt[c];
                Ys[r * 128 + c] = o > 0.f ? tanhf(o) : 0.f;
            }
        }
        __syncthreads();

        float acc2[16][2];
        {
            float bb0 = __ldg(&b2p[2 * lane]), bb1 = __ldg(&b2p[2 * lane + 1]);
#pragma unroll
            for (int j = 0; j < 16; j++) { acc2[j][0] = bb0; acc2[j][1] = bb1; }
        }
        for (int k4 = 0; k4 < 32; k4++) {
            float2 w[4];
#pragma unroll
            for (int q = 0; q < 4; q++)
                w[q] = *(const float2*)&W2s[(k4 * 4 + q) * 64 + 2 * lane];
#pragma unroll
            for (int j = 0; j < 16; j++) {
                float4 xv = *(const float4*)&Ys[(wid * 16 + j) * 128 + k4 * 4];
                acc2[j][0] = fmaf(xv.x, w[0].x, acc2[j][0]);
                acc2[j][1] = fmaf(xv.x, w[0].y, acc2[j][1]);
                acc2[j][0] = fmaf(xv.y, w[1].x, acc2[j][0]);
                acc2[j][1] = fmaf(xv.y, w[1].y, acc2[j][1]);
                acc2[j][0] = fmaf(xv.z, w[2].x, acc2[j][0]);
                acc2[j][1] = fmaf(xv.z, w[2].y, acc2[j][1]);
                acc2[j][0] = fmaf(xv.w, w[3].x, acc2[j][0]);
                acc2[j][1] = fmaf(xv.w, w[3].y, acc2[j][1]);
            }
        }

        float gg0 = __ldg(&g2p[2 * lane]), gg1 = __ldg(&g2p[2 * lane + 1]);
        float bt0 = __ldg(&bn2p[2 * lane]), bt1 = __ldg(&bn2p[2 * lane + 1]);
        float w30a = W3s[(2 * lane) * 3 + 0], w31a = W3s[(2 * lane) * 3 + 1],
              w32a = W3s[(2 * lane) * 3 + 2];
        float w30b = W3s[(2 * lane + 1) * 3 + 0], w31b = W3s[(2 * lane + 1) * 3 + 1],
              w32b = W3s[(2 * lane + 1) * 3 + 2];
        for (int j = 0; j < 16; j++) {
            float a = acc2[j][0], b = acc2[j][1];
            float s = a + b;
            float s2 = fmaf(a, a, b * b);
#pragma unroll
            for (int off = 16; off; off >>= 1) {
                s  += __shfl_xor_sync(0xffffffffu, s, off);
                s2 += __shfl_xor_sync(0xffffffffu, s2, off);
            }
            float mu = s * (1.f / 64.f);
            float var = s2 * (1.f / 64.f) - mu * mu;
            float rs = rsqrtf(fmaxf(var, 0.f) + 1e-5f);
            float va = (a - mu) * rs * gg0 + bt0;
            float vb = (b - mu) * rs * gg1 + bt1;
            va = va > 0.f ? va : 0.f;
            vb = vb > 0.f ? vb : 0.f;
            float o0 = fmaf(va, w30a, vb * w30b);
            float o1 = fmaf(va, w31a, vb * w31b);
            float o2 = fmaf(va, w32a, vb * w32b);
#pragma unroll
            for (int off = 16; off; off >>= 1) {
                o0 += __shfl_down_sync(0xffffffffu, o0, off);
                o1 += __shfl_down_sync(0xffffffffu, o1, off);
                o2 += __shfl_down_sync(0xffffffffu, o2, off);
            }
            int grow = mBase + wid * 16 + j;
            if (lane == 0 && grow < M) {
                o0 += b3s[0];
                o1 += b3s[1];
                o2 += b3s[2];
                float sq = o0 * o0 + o1 * o1 + o2 * o2;
                g_h4[grow] = make_float4(o0, o1, o2, sq);
            }
        }
    }
}

// ------------------------- per-edge softmax weights (one warp per dst) -------------------------
__device__ __forceinline__ float lrelu02(float x) { return x > 0.f ? x : 0.2f * x; }

__global__ void k_alpha() {
    int gw = (blockIdx.x * blockDim.x + threadIdx.x) >> 5;
    int lane = threadIdx.x & 31;
    if (gw >= NN) return;
    int s0 = g_rowptr[gw], s1 = g_rowptr[gw + 1];
    float ad0 = g_ad[gw * 2], ad1 = g_ad[gw * 2 + 1];
    float m0 = -1e30f, m1 = -1e30f;
    for (int i = s0 + lane; i < s1; i += 32) {
        int s = g_csr[i];
        m0 = fmaxf(m0, lrelu02(g_as[s * 2] + ad0));
        m1 = fmaxf(m1, lrelu02(g_as[s * 2 + 1] + ad1));
    }
#pragma unroll
    for (int off = 16; off; off >>= 1) {
        m0 = fmaxf(m0, __shfl_xor_sync(0xffffffffu, m0, off));
        m1 = fmaxf(m1, __shfl_xor_sync(0xffffffffu, m1, off));
    }
    float z0 = 0.f, z1 = 0.f;
    for (int i = s0 + lane; i < s1; i += 32) {
        int s = g_csr[i];
        float w0 = __expf(lrelu02(g_as[s * 2] + ad0) - m0);
        float w1 = __expf(lrelu02(g_as[s * 2 + 1] + ad1) - m1);
        g_w2[i] = make_float2(w0, w1);
        z0 += w0;
        z1 += w1;
    }
#pragma unroll
    for (int off = 16; off; off >>= 1) {
        z0 += __shfl_xor_sync(0xffffffffu, z0, off);
        z1 += __shfl_xor_sync(0xffffffffu, z1, off);
    }
    if (lane == 0) {
        g_zi[gw * 2]     = 1.f / (z0 + 1e-16f);
        g_zi[gw * 2 + 1] = 1.f / (z1 + 1e-16f);
    }
}

// ------------------------- aggregate (fp16 gather, 8x unrolled) + relu + bf16 split -------------------------
__device__ __forceinline__ void agg_edge4(int i, int head, int t, float4& acc) {
    int sa = g_csr[i], sb = g_csr[i + 1], sc = g_csr[i + 2], sd = g_csr[i + 3];
    float2 wa2 = g_w2[i], wb2 = g_w2[i + 1], wc2 = g_w2[i + 2], wd2 = g_w2[i + 3];
    float wa = head ? wa2.y : wa2.x;
    float wb = head ? wb2.y : wb2.x;
    float wc = head ? wc2.y : wc2.x;
    float wd = head ? wd2.y : wd2.x;
    uint2 ua = *(const uint2*)&g_Hh[(size_t)sa * 512 + t * 4];
    uint2 ub = *(const uint2*)&g_Hh[(size_t)sb * 512 + t * 4];
    uint2 uc = *(const uint2*)&g_Hh[(size_t)sc * 512 + t * 4];
    uint2 ud = *(const uint2*)&g_Hh[(size_t)sd * 512 + t * 4];
    float2 a01 = __half22float2(*(__half2*)&ua.x), a23 = __half22float2(*(__half2*)&ua.y);
    float2 b01 = __half22float2(*(__half2*)&ub.x), b23 = __half22float2(*(__half2*)&ub.y);
    float2 c01 = __half22float2(*(__half2*)&uc.x), c23 = __half22float2(*(__half2*)&uc.y);
    float2 d01 = __half22float2(*(__half2*)&ud.x), d23 = __half22float2(*(__half2*)&ud.y);
    acc.x = fmaf(wa, a01.x, fmaf(wb, b01.x, fmaf(wc, c01.x, fmaf(wd, d01.x, acc.x))));
    acc.y = fmaf(wa, a01.y, fmaf(wb, b01.y, fmaf(wc, c01.y, fmaf(wd, d01.y, acc.y))));
    acc.z = fmaf(wa, a23.x, fmaf(wb, b23.x, fmaf(wc, c23.x, fmaf(wd, d23.x, acc.z))));
    acc.w = fmaf(wa, a23.y, fmaf(wb, b23.y, fmaf(wc, c23.y, fmaf(wd, d23.y, acc.w))));
}

__global__ void k_agg2(const float* __restrict__ bgat) {
    int n = blockIdx.x;
    int t = threadIdx.x;  // 128 threads, 4 channels each
    int head = t >> 6;
    int s0 = g_rowptr[n], s1 = g_rowptr[n + 1];
    float4 acc = make_float4(0.f, 0.f, 0.f, 0.f);
    int i = s0;
    for (; i + 8 <= s1; i += 8) {
        agg_edge4(i, head, t, acc);
        agg_edge4(i + 4, head, t, acc);
    }
    for (; i + 4 <= s1; i += 4) {
        agg_edge4(i, head, t, acc);
    }
    for (; i < s1; i++) {
        int s = g_csr[i];
        float2 w2 = g_w2[i];
        float w = head ? w2.y : w2.x;
        uint2 u = *(const uint2*)&g_Hh[(size_t)s * 512 + t * 4];
        float2 h01 = __half22float2(*(__half2*)&u.x), h23 = __half22float2(*(__half2*)&u.y);
        acc.x = fmaf(w, h01.x, acc.x);
        acc.y = fmaf(w, h01.y, acc.y);
        acc.z = fmaf(w, h23.x, acc.z);
        acc.w = fmaf(w, h23.y, acc.w);
    }
    float zi = g_zi[n * 2 + head];
    float4 b4 = *(const float4*)&bgat[t * 4];
    float4 o;
    o.x = fmaf(acc.x, zi, b4.x);
    o.y = fmaf(acc.y, zi, b4.y);
    o.z = fmaf(acc.z, zi, b4.z);
    o.w = fmaf(acc.w, zi, b4.w);
    o.x = o.x > 0.f ? o.x : 0.f;
    o.y = o.y > 0.f ? o.y : 0.f;
    o.z = o.z > 0.f ? o.z : 0.f;
    o.w = o.w > 0.f ? o.w : 0.f;
    __nv_bfloat16 h0 = __float2bfloat16_rn(o.x), h1 = __float2bfloat16_rn(o.y);
    __nv_bfloat16 h2 = __float2bfloat16_rn(o.z), h3 = __float2bfloat16_rn(o.w);
    float l0 = o.x - __bfloat162float(h0), l1 = o.y - __bfloat162float(h1);
    float l2 = o.z - __bfloat162float(h2), l3 = o.w - __bfloat162float(h3);
    uint32_t hp0 = (((uint32_t)*(uint16_t*)&h1) << 16) | (uint32_t)*(uint16_t*)&h0;
    uint32_t hp1 = (((uint32_t)*(uint16_t*)&h3) << 16) | (uint32_t)*(uint16_t*)&h2;
    ((uint2*)g_Xhi)[n * 128 + t] = make_uint2(hp0, hp1);
    ((uint2*)g_Xlo)[n * 128 + t] = make_uint2(pack_bf2(l0, l1), pack_bf2(l2, l3));
}

// ------------------------- bias + LN + relu epilogue, bf16 split out (layerA) -------------------------
__global__ void k_ln_act256(const float* __restrict__ pre, const float* __restrict__ bias,
                            const float* __restrict__ gam, const float* __restrict__ bet,
                            __nv_bfloat16* __restrict__ oHi, __nv_bfloat16* __restrict__ oLo) {
    int row = blockIdx.x * 8 + (threadIdx.x >> 5);
    int lane = threadIdx.x & 31;
    if (row >= NN) return;
    const float* p = pre + (size_t)row * 256;
    float v[8];
    float s = 0.f, s2 = 0.f;
#pragma unroll
    for (int j = 0; j < 8; j++) {
        int c = lane + j * 32;
        v[j] = p[c] + bias[c];
        s += v[j];
        s2 = fmaf(v[j], v[j], s2);
    }
#pragma unroll
    for (int off = 16; off; off >>= 1) {
        s  += __shfl_xor_sync(0xffffffffu, s, off);
        s2 += __shfl_xor_sync(0xffffffffu, s2, off);
    }
    float mu = s * (1.f / 256.f);
    float var = s2 * (1.f / 256.f) - mu * mu;
    float rs = rsqrtf(fmaxf(var, 0.f) + 1e-5f);
#pragma unroll
    for (int j = 0; j < 8; j++) {
        int c = lane + j * 32;
        float o = (v[j] - mu) * rs * gam[c] + bet[c];
        o = o > 0.f ? o : 0.f;
        __nv_bfloat16 h = __float2bfloat16_rn(o);
        float l = o - __bfloat162float(h);
        oHi[(size_t)row * 256 + c] = h;
        oLo[(size_t)row * 256 + c] = __float2bfloat16_rn(l);
    }
}

// ------------------------- pairwise distance (MUFU.SQRT, streaming stores) -------------------------
__device__ __forceinline__ float pdist(float4 a, float4 b) {
    float dot = fmaf(a.x, b.x, fmaf(a.y, b.y, a.z * b.z));
    float d = fmaf(-2.f, dot, a.w + b.w);
    return fsqrt_ap(fmaxf(d, 0.f));
}

__global__ void k_cdist(float* __restrict__ out) {
    int j4 = blockIdx.x * blockDim.x + threadIdx.x;
    if (j4 >= NN / 4) return;
    int i0 = blockIdx.y * 4;
    float4 bq0 = g_h4[4 * j4 + 0];
    float4 bq1 = g_h4[4 * j4 + 1];
    float4 bq2 = g_h4[4 * j4 + 2];
    float4 bq3 = g_h4[4 * j4 + 3];
#pragma unroll
    for (int r = 0; r < 4; r++) {
        float4 a = g_h4[i0 + r];
        float4 o = make_float4(pdist(a, bq0), pdist(a, bq1), pdist(a, bq2), pdist(a, bq3));
        __stcs((float4*)(out + (size_t)(i0 + r) * NN + 4 * j4), o);
    }
}

// ------------------------- streams -------------------------
static cudaStream_t s_edge = nullptr, s_wts = nullptr;
static cudaEvent_t ev_start = nullptr, ev_edge = nullptr, ev_wts = nullptr, ev_wts2 = nullptr;
struct HxInit {
    HxInit() {
        cudaStreamCreateWithFlags(&s_edge, cudaStreamNonBlocking);
        cudaStreamCreateWithFlags(&s_wts, cudaStreamNonBlocking);
        cudaEventCreateWithFlags(&ev_start, cudaEventDisableTiming);
        cudaEventCreateWithFlags(&ev_edge, cudaEventDisableTiming);
        cudaEventCreateWithFlags(&ev_wts, cudaEventDisableTiming);
        cudaEventCreateWithFlags(&ev_wts2, cudaEventDisableTiming);
    }
};
static HxInit g_hxinit;

// ------------------------- launch -------------------------
extern "C" void kernel_launch(void* const* d_in, const int* in_sizes, int n_in,
                              void* d_out, int out_size) {
    const float* x      = (const float*)d_in[0];
    const void*  ei     = d_in[1];
    const float* W_gat  = (const float*)d_in[2];
    const float* attS   = (const float*)d_in[3];
    const float* attD   = (const float*)d_in[4];
    const float* b_gat  = (const float*)d_in[5];
    const float* Wa     = (const float*)d_in[6];
    const float* ba     = (const float*)d_in[7];
    const float* ga     = (const float*)d_in[8];
    const float* bna    = (const float*)d_in[9];
    const float* W1     = (const float*)d_in[10];
    const float* b1     = (const float*)d_in[11];
    const float* g1     = (const float*)d_in[12];
    const float* bn1    = (const float*)d_in[13];
    const float* W2     = (const float*)d_in[14];
    const float* b2     = (const float*)d_in[15];
    const float* g2     = (const float*)d_in[16];
    const float* bn2    = (const float*)d_in[17];
    const float* W3     = (const float*)d_in[18];
    const float* b3     = (const float*)d_in[19];
    float* out = (float*)d_out;

    int E = in_sizes[1] / 2;
    int tot = E + NN;

    static float* pPre = nullptr;
    static int* pCnt = nullptr;
    static __nv_bfloat16 *pBhi = nullptr, *pBlo = nullptr, *pBhi2 = nullptr, *pBlo2 = nullptr,
                         *pBhiW1 = nullptr, *pBloW1 = nullptr, *pXhi = nullptr, *pXlo = nullptr;
    static bool attrDone = false;
    if (!pPre) {
        cudaGetSymbolAddress((void**)&pPre, g_pre);
        cudaGetSymbolAddress((void**)&pCnt, g_cnt);
        cudaGetSymbolAddress((void**)&pBhi, g_Bhi);
        cudaGetSymbolAddress((void**)&pBlo, g_Blo);
        cudaGetSymbolAddress((void**)&pBhi2, g_Bhi2);
        cudaGetSymbolAddress((void**)&pBlo2, g_Blo2);
        cudaGetSymbolAddress((void**)&pBhiW1, g_BhiW1);
        cudaGetSymbolAddress((void**)&pBloW1, g_BloW1);
        cudaGetSymbolAddress((void**)&pXhi, g_Xhi);
        cudaGetSymbolAddress((void**)&pXlo, g_Xlo);
    }
    if (!attrDone) {
        cudaFuncSetAttribute((const void*)k_gemm_mma<512, 512, 3>,
                             cudaFuncAttributeMaxDynamicSharedMemorySize, 2 * GSTAGE);
        cudaFuncSetAttribute((const void*)k_gemm_mma<512, 256, 0>,
                             cudaFuncAttributeMaxDynamicSharedMemorySize, 2 * GSTAGE);
        cudaFuncSetAttribute((const void*)k_gemm_mma<256, 128, 1>,
                             cudaFuncAttributeMaxDynamicSharedMemorySize, 2 * GSTAGE);
        attrDone = true;
    }

    // fork
    cudaEventRecord(ev_start, 0);
    cudaStreamWaitEvent(s_edge, ev_start, 0);
    cudaStreamWaitEvent(s_wts, ev_start, 0);

    // edge + attention-weight chain (stream E)
    cudaMemsetAsync(pCnt, 0, NN * sizeof(int), s_edge);
    k_detect<<<1, 1, 0, s_edge>>>(ei);
    k_convert<<<(tot + 255) / 256, 256, 0, s_edge>>>(ei, E);
    k_scan<<<1, 1024, 0, s_edge>>>();
    k_scatter<<<(tot + 255) / 256, 256, 0, s_edge>>>(tot);
    k_attvec<<<128, 256, 0, s_edge>>>(W_gat, attS, attD);
    k_attdot2<<<(NN * 32 + 255) / 256, 256, 0, s_edge>>>(x);
    k_alpha<<<(NN * 32 + 255) / 256, 256, 0, s_edge>>>();
    cudaEventRecord(ev_edge, s_edge);

    // weight splits (stream W)
    k_prepWT<<<512, 256, 0, s_wts>>>(W_gat, 512, 512, pBhi, pBlo);
    cudaEventRecord(ev_wts, s_wts);
    k_prepWT<<<256, 256, 0, s_wts>>>(Wa, 512, 256, pBhi2, pBlo2);
    k_prepWT<<<128, 256, 0, s_wts>>>(W1, 256, 128, pBhiW1, pBloW1);
    cudaEventRecord(ev_wts2, s_wts);

    // main pipeline (origin stream)
    int n4x = NN * 512 / 4;
    k_split<<<(n4x + 255) / 256, 256>>>((const float4*)x, (uint2*)pXhi, (uint2*)pXlo, n4x);
    cudaStreamWaitEvent(0, ev_wts, 0);
    {
        dim3 gg(4, (NN + 127) / 128);
        k_gemm_mma<512, 512, 3><<<gg, 256, 2 * GSTAGE>>>(
            pXhi, pXlo, pBhi, pBlo, nullptr, NN, nullptr, nullptr, nullptr,
            nullptr, nullptr, nullptr, nullptr, nullptr, nullptr);
    }

    cudaStreamWaitEvent(0, ev_edge, 0);
    k_agg2<<<NN, 128>>>(b_gat);   // fp16 gather; emits bf16 hi/lo into g_Xhi/g_Xlo

    cudaStreamWaitEvent(0, ev_wts2, 0);
    // layer A: pre = gat @ Wa  -> LN+relu -> hi/lo split
    {
        dim3 gg(2, (NN + 127) / 128);
        k_gemm_mma<512, 256, 0><<<gg, 256, 2 * GSTAGE>>>(
            pXhi, pXlo, pBhi2, pBlo2, pPre, NN, nullptr, nullptr, nullptr,
            nullptr, nullptr, nullptr, nullptr, nullptr, nullptr);
    }
    k_ln_act256<<<(NN + 7) / 8, 256>>>(pPre, ba, ga, bna, pXhi, pXlo);

    // layer 1 GEMM with fully fused tail (LN+tanh -> layer2 -> LN+relu -> layer3 -> g_h4)
    {
        dim3 gg(1, (NN + 127) / 128);
        k_gemm_mma<256, 128, 1><<<gg, 256, 2 * GSTAGE>>>(
            pXhi, pXlo, pBhiW1, pBloW1, nullptr, NN, b1, g1, bn1,
            W2, b2, g2, bn2, W3, b3);
    }

    dim3 gc((NN / 4 + 255) / 256, NN / 4);
    k_cdist<<<gc, 256>>>(out);
}

// round 17
// speedup vs baseline: 1.5149x; 1.0076x over previous
#include <cuda_runtime.h>
#include <cuda_bf16.h>
#include <cuda_fp16.h>
#include <math.h>
#include <stdint.h>

#define NN 10000
#define EMAX 400000

// ------------------------- scratch (static device globals) -------------------------
__device__ int   g_flag64;
__device__ int   g_src[EMAX];
__device__ int   g_dstA[EMAX];
__device__ int   g_cnt[NN];
__device__ int   g_rowptr[NN + 1];
__device__ int   g_cursor[NN];
__device__ int   g_csr[EMAX];
__device__ __half g_Hh[NN * 512];    // x @ W_gat, fp16 (halves agg gather traffic)
__device__ float g_as[NN * 2];
__device__ float g_ad[NN * 2];
__device__ float g_vas[512 * 2];     // W_gat @ att_src  [k][h]
__device__ float g_vad[512 * 2];     // W_gat @ att_dst  [k][h]
__device__ float g_pre[NN * 256];    // pre-LN buffer (layerA)
__device__ float4 g_h4[NN];
__device__ float2 g_w2[EMAX];
__device__ float  g_zi[NN * 2];
__device__ __nv_bfloat16 g_Bhi[512 * 512];    // W_gat^T hi  [n][k]
__device__ __nv_bfloat16 g_Blo[512 * 512];    // W_gat^T lo
__device__ __nv_bfloat16 g_Bhi2[256 * 512];   // Wa^T hi
__device__ __nv_bfloat16 g_Blo2[256 * 512];   // Wa^T lo
__device__ __nv_bfloat16 g_BhiW1[128 * 256];  // W1^T hi
__device__ __nv_bfloat16 g_BloW1[128 * 256];  // W1^T lo
__device__ __nv_bfloat16 g_Xhi[NN * 512];     // activations hi [m][k]
__device__ __nv_bfloat16 g_Xlo[NN * 512];     // activations lo

// ------------------------- helpers -------------------------
__device__ __forceinline__ uint32_t smem_u32(const void* p) {
    uint32_t a;
    asm("{ .reg .u64 t; cvta.to.shared.u64 t, %1; cvt.u32.u64 %0, t; }" : "=r"(a) : "l"(p));
    return a;
}
__device__ __forceinline__ void cp16(const void* smem_dst, const void* gsrc) {
    uint32_t s = smem_u32(smem_dst);
    asm volatile("cp.async.cg.shared.global [%0], [%1], 16;" :: "r"(s), "l"(gsrc));
}
#define CP_COMMIT() asm volatile("cp.async.commit_group;" ::: "memory")
#define CP_WAIT0()  asm volatile("cp.async.wait_group 0;" ::: "memory")
#define CP_WAIT1()  asm volatile("cp.async.wait_group 1;" ::: "memory")

__device__ __forceinline__ void mma_bf16(float* c, const uint32_t* a, const uint32_t* b) {
    asm volatile(
        "mma.sync.aligned.m16n8k16.row.col.f32.bf16.bf16.f32 "
        "{%0,%1,%2,%3}, {%4,%5,%6,%7}, {%8,%9}, {%0,%1,%2,%3};"
        : "+f"(c[0]), "+f"(c[1]), "+f"(c[2]), "+f"(c[3])
        : "r"(a[0]), "r"(a[1]), "r"(a[2]), "r"(a[3]), "r"(b[0]), "r"(b[1]));
}
__device__ __forceinline__ uint32_t pack_bf2(float a, float b) {
    __nv_bfloat162 t = __floats2bfloat162_rn(a, b);
    return *(uint32_t*)&t;
}
__device__ __forceinline__ float fsqrt_ap(float x) {
    float y;
    asm("sqrt.approx.f32 %0, %1;" : "=f"(y) : "f"(x));
    return y;
}

// ------------------------- edge dtype detect + convert -------------------------
__global__ void k_detect(const void* ei) {
    const long long* p = (const long long*)ei;
    int ok = 1;
    for (int i = 0; i < 8; i++) {
        long long v = p[i];
        if (v < 0 || v >= NN) ok = 0;
    }
    g_flag64 = ok;
}

__global__ void k_convert(const void* ei, int E) {
    int i = blockIdx.x * blockDim.x + threadIdx.x;
    int tot = E + NN;
    if (i >= tot || i >= EMAX) return;
    int s, d;
    if (i < E) {
        if (g_flag64) {
            const long long* p = (const long long*)ei;
            s = (int)p[i];
            d = (int)p[E + i];
        } else {
            const int* p = (const int*)ei;
            s = p[i];
            d = p[E + i];
        }
    } else {
        s = d = i - E;
    }
    g_src[i] = s;
    g_dstA[i] = d;
    atomicAdd(&g_cnt[d], 1);
}

// fast single-block exclusive scan
__global__ void k_scan() {
    __shared__ int wsum[32];
    int tid = threadIdx.x;
    int lane = tid & 31, warp = tid >> 5;
    int base = tid * 10;
    int v[10];
    int s = 0;
#pragma unroll
    for (int j = 0; j < 10; j++) {
        int idx = base + j;
        v[j] = (idx < NN) ? g_cnt[idx] : 0;
        s += v[j];
    }
    int x = s;
#pragma unroll
    for (int off = 1; off < 32; off <<= 1) {
        int t = __shfl_up_sync(0xffffffffu, x, off);
        if (lane >= off) x += t;
    }
    if (lane == 31) wsum[warp] = x;
    __syncthreads();
    if (warp == 0) {
        int y = wsum[lane];
#pragma unroll
        for (int off = 1; off < 32; off <<= 1) {
            int t = __shfl_up_sync(0xffffffffu, y, off);
            if (lane >= off) y += t;
        }
        wsum[lane] = y;
    }
    __syncthreads();
    int excl = x - s + (warp ? wsum[warp - 1] : 0);
    int run = excl;
#pragma unroll
    for (int j = 0; j < 10; j++) {
        int idx = base + j;
        if (idx < NN) {
            g_rowptr[idx] = run;
            g_cursor[idx] = run;
            run += v[j];
        }
    }
    if (tid == 1023) g_rowptr[NN] = run;
}

__global__ void k_scatter(int tot) {
    int i = blockIdx.x * blockDim.x + threadIdx.x;
    if (i >= tot || i >= EMAX) return;
    int d = g_dstA[i];
    int pos = atomicAdd(&g_cursor[d], 1);
    g_csr[pos] = g_src[i];
}

// ------------------------- fp32 -> bf16 hi/lo split -------------------------
__global__ void k_split(const float4* __restrict__ X, uint2* __restrict__ hi,
                        uint2* __restrict__ lo, int n4) {
    int i = blockIdx.x * blockDim.x + threadIdx.x;
    if (i >= n4) return;
    float4 v = X[i];
    __nv_bfloat16 h0 = __float2bfloat16_rn(v.x), h1 = __float2bfloat16_rn(v.y);
    __nv_bfloat16 h2 = __float2bfloat16_rn(v.z), h3 = __float2bfloat16_rn(v.w);
    float l0 = v.x - __bfloat162float(h0), l1 = v.y - __bfloat162float(h1);
    float l2 = v.z - __bfloat162float(h2), l3 = v.w - __bfloat162float(h3);
    uint32_t hp0 = (((uint32_t)*(uint16_t*)&h1) << 16) | (uint32_t)*(uint16_t*)&h0;
    uint32_t hp1 = (((uint32_t)*(uint16_t*)&h3) << 16) | (uint32_t)*(uint16_t*)&h2;
    hi[i] = make_uint2(hp0, hp1);
    lo[i] = make_uint2(pack_bf2(l0, l1), pack_bf2(l2, l3));
}

// W [K][N] -> B^T hi/lo [n][k]
__global__ void k_prepWT(const float* __restrict__ W, int K, int N,
                         __nv_bfloat16* __restrict__ Bh, __nv_bfloat16* __restrict__ Bl) {
    int n = blockIdx.x;
    for (int k = threadIdx.x; k < K; k += blockDim.x) {
        float v = W[(size_t)k * N + n];
        __nv_bfloat16 h = __float2bfloat16_rn(v);
        float r = v - __bfloat162float(h);
        Bh[(size_t)n * K + k] = h;
        Bl[(size_t)n * K + k] = __float2bfloat16_rn(r);
    }
}

// ------------------------- attention vectors: va = W_gat @ att (per head) -------------------------
__global__ void k_attvec(const float* __restrict__ W, const float* __restrict__ attS,
                         const float* __restrict__ attD) {
    int idx = (blockIdx.x * blockDim.x + threadIdx.x) >> 5;
    int lane = threadIdx.x & 31;
    if (idx >= 1024) return;
    int k = idx >> 1, h = idx & 1;
    const float* wrow = W + (size_t)k * 512 + h * 256;
    const float* as = attS + h * 256;
    const float* ad = attD + h * 256;
    float s = 0.f, d = 0.f;
#pragma unroll
    for (int j = 0; j < 8; j++) {
        int c = lane + j * 32;
        float w = wrow[c];
        s = fmaf(w, __ldg(&as[c]), s);
        d = fmaf(w, __ldg(&ad[c]), d);
    }
#pragma unroll
    for (int off = 16; off; off >>= 1) {
        s += __shfl_xor_sync(0xffffffffu, s, off);
        d += __shfl_xor_sync(0xffffffffu, d, off);
    }
    if (lane == 0) {
        g_vas[k * 2 + h] = s;
        g_vad[k * 2 + h] = d;
    }
}

// ------------------------- attention dots from x directly -------------------------
__global__ void k_attdot2(const float* __restrict__ x) {
    int node = (blockIdx.x * blockDim.x + threadIdx.x) >> 5;
    int lane = threadIdx.x & 31;
    if (node >= NN) return;
    const float* xr = x + (size_t)node * 512;
    float s0 = 0.f, s1 = 0.f, d0 = 0.f, d1 = 0.f;
#pragma unroll
    for (int j = 0; j < 16; j++) {
        int k = lane + j * 32;
        float xv = xr[k];
        s0 = fmaf(xv, g_vas[k * 2], s0);
        s1 = fmaf(xv, g_vas[k * 2 + 1], s1);
        d0 = fmaf(xv, g_vad[k * 2], d0);
        d1 = fmaf(xv, g_vad[k * 2 + 1], d1);
    }
#pragma unroll
    for (int off = 16; off; off >>= 1) {
        s0 += __shfl_xor_sync(0xffffffffu, s0, off);
        s1 += __shfl_xor_sync(0xffffffffu, s1, off);
        d0 += __shfl_xor_sync(0xffffffffu, d0, off);
        d1 += __shfl_xor_sync(0xffffffffu, d1, off);
    }
    if (lane == 0) {
        g_as[node * 2] = s0;
        g_as[node * 2 + 1] = s1;
        g_ad[node * 2] = d0;
        g_ad[node * 2 + 1] = d1;
    }
}

// ------------------------- bf16x3 GEMM via mma.sync -------------------------
// EPI 0: plain fp32 store.
// EPI 1: full fused tail (NTOT==128): bias+LN(128)+tanh(relu) -> layer2 + LN(64)+relu -> layer3 -> g_h4
// EPI 3: fp16 store to g_Hh (ldc = NTOT)
#define GTILE 18432                 // one 128x(64+8pad) bf16 tile
#define GSTAGE (4 * GTILE)
#define GLDS 144                    // bytes per smem row (72 bf16)

template <int KTOT, int NTOT, int EPI>
__global__ __launch_bounds__(256) void k_gemm_mma(
    const __nv_bfloat16* __restrict__ Ah, const __nv_bfloat16* __restrict__ Al,
    const __nv_bfloat16* __restrict__ Bh, const __nv_bfloat16* __restrict__ Bl,
    float* __restrict__ C, int M,
    const float* __restrict__ lnb, const float* __restrict__ lng,
    const float* __restrict__ lnbt,
    const float* __restrict__ W2p, const float* __restrict__ b2p,
    const float* __restrict__ g2p, const float* __restrict__ bn2p,
    const float* __restrict__ W3p, const float* __restrict__ b3p) {
    constexpr int STAGES = KTOT / 64;
    extern __shared__ char sm[];
    const int tid = threadIdx.x;
    const int wid = tid >> 5, lane = tid & 31;
    const int g = lane >> 2, tg = lane & 3;
    const int warpM = wid & 3, warpN = wid >> 2;
    const int mBase = blockIdx.y * 128;
    const int nBase = blockIdx.x * 128;

    float acc[2][8][4];
#pragma unroll
    for (int a = 0; a < 2; a++)
#pragma unroll
        for (int b = 0; b < 8; b++)
#pragma unroll
            for (int c = 0; c < 4; c++) acc[a][b][c] = 0.f;

    auto load_stage = [&](int buf, int k0) {
        char* st = sm + buf * GSTAGE;
#pragma unroll
        for (int t = 0; t < 4; t++) {
            int idx = tid + t * 256;
            int row = idx >> 3, seg = idx & 7;
            int gr = mBase + row;
            if (gr > M - 1) gr = M - 1;
            size_t ga = (size_t)gr * KTOT + k0 + seg * 8;
            size_t gb = (size_t)(nBase + row) * KTOT + k0 + seg * 8;
            uint32_t so = row * GLDS + seg * 16;
            cp16(st + so, Ah + ga);
            cp16(st + GTILE + so, Al + ga);
            cp16(st + 2 * GTILE + so, Bh + gb);
            cp16(st + 3 * GTILE + so, Bl + gb);
        }
    };

    load_stage(0, 0);
    CP_COMMIT();

    for (int s = 0; s < STAGES; s++) {
        if (s + 1 < STAGES) {
            load_stage((s + 1) & 1, (s + 1) * 64);
            CP_COMMIT();
            CP_WAIT1();
        } else {
            CP_WAIT0();
        }
        __syncthreads();
        const char* st = sm + (s & 1) * GSTAGE;
#pragma unroll
        for (int ks = 0; ks < 4; ks++) {
            int k2 = ks * 16 + tg * 2;
            uint32_t ah[2][4], al[2][4];
#pragma unroll
            for (int ms = 0; ms < 2; ms++) {
                int r0 = warpM * 32 + ms * 16 + g;
                const char* pa = st + r0 * GLDS + k2 * 2;
                ah[ms][0] = *(const uint32_t*)(pa);
                ah[ms][1] = *(const uint32_t*)(pa + 8 * GLDS);
                ah[ms][2] = *(const uint32_t*)(pa + 16);
                ah[ms][3] = *(const uint32_t*)(pa + 8 * GLDS + 16);
                const char* pl = pa + GTILE;
                al[ms][0] = *(const uint32_t*)(pl);
                al[ms][1] = *(const uint32_t*)(pl + 8 * GLDS);
                al[ms][2] = *(const uint32_t*)(pl + 16);
                al[ms][3] = *(const uint32_t*)(pl + 8 * GLDS + 16);
            }
            uint32_t bh[8][2], bl[8][2];
#pragma unroll
            for (int ns = 0; ns < 8; ns++) {
                int r = warpN * 64 + ns * 8 + g;
                const char* pb = st + 2 * GTILE + r * GLDS + k2 * 2;
                bh[ns][0] = *(const uint32_t*)(pb);
                bh[ns][1] = *(const uint32_t*)(pb + 16);
                bl[ns][0] = *(const uint32_t*)(pb + GTILE);
                bl[ns][1] = *(const uint32_t*)(pb + GTILE + 16);
            }
#pragma unroll
            for (int ms = 0; ms < 2; ms++)
#pragma unroll
                for (int ns = 0; ns < 8; ns++) {
                    mma_bf16(acc[ms][ns], ah[ms], bh[ns]);
                    mma_bf16(acc[ms][ns], ah[ms], bl[ns]);
                    mma_bf16(acc[ms][ns], al[ms], bh[ns]);
                }
        }
        __syncthreads();
    }

    if (EPI == 0) {
#pragma unroll
        for (int ms = 0; ms < 2; ms++) {
            int row = mBase + warpM * 32 + ms * 16 + g;
#pragma unroll
            for (int ns = 0; ns < 8; ns++) {
                int col = nBase + warpN * 64 + ns * 8 + tg * 2;
                if (col >= NTOT) continue;
                if (row < M)
                    *(float2*)&C[(size_t)row * NTOT + col] =
                        make_float2(acc[ms][ns][0], acc[ms][ns][1]);
                if (row + 8 < M)
                    *(float2*)&C[(size_t)(row + 8) * NTOT + col] =
                        make_float2(acc[ms][ns][2], acc[ms][ns][3]);
            }
        }
    } else if (EPI == 3) {
        // fp16 store into g_Hh
#pragma unroll
        for (int ms = 0; ms < 2; ms++) {
            int row = mBase + warpM * 32 + ms * 16 + g;
#pragma unroll
            for (int ns = 0; ns < 8; ns++) {
                int col = nBase + warpN * 64 + ns * 8 + tg * 2;
                if (row < M) {
                    __half2 p = __floats2half2_rn(acc[ms][ns][0], acc[ms][ns][1]);
                    *(__half2*)&g_Hh[(size_t)row * NTOT + col] = p;
                }
                if (row + 8 < M) {
                    __half2 p = __floats2half2_rn(acc[ms][ns][2], acc[ms][ns][3]);
                    *(__half2*)&g_Hh[(size_t)(row + 8) * NTOT + col] = p;
                }
            }
        }
    } else {
        // ---- full fused tail: LN(128)+tanh(relu) -> layer2 -> LN(64)+relu -> layer3 -> g_h4
        float* Ys  = (float*)sm;               // 128 x 128 fp32 (64 KB)
        float* W2s = (float*)(sm + 65536);     // 128 x 64 fp32 (32 KB)
        __shared__ float W3s[192];
        __shared__ float b3s[3];

#pragma unroll
        for (int ms = 0; ms < 2; ms++) {
            int r = warpM * 32 + ms * 16 + g;
#pragma unroll
            for (int ns = 0; ns < 8; ns++) {
                int c = warpN * 64 + ns * 8 + tg * 2;
                Ys[r * 128 + c] = acc[ms][ns][0];
                Ys[r * 128 + c + 1] = acc[ms][ns][1];
                Ys[(r + 8) * 128 + c] = acc[ms][ns][2];
                Ys[(r + 8) * 128 + c + 1] = acc[ms][ns][3];
            }
        }
        for (int i = tid; i < 128 * 64; i += 256) W2s[i] = W2p[i];
        if (tid < 192) W3s[tid] = W3p[tid];
        if (tid < 3) b3s[tid] = b3p[tid];
        __syncthreads();

        for (int rr = 0; rr < 16; rr++) {
            int r = wid * 16 + rr;
            float v[4];
            float s = 0.f, s2 = 0.f;
#pragma unroll
            for (int j = 0; j < 4; j++) {
                int c = lane + j * 32;
                v[j] = Ys[r * 128 + c] + lnb[c];
                s += v[j];
                s2 = fmaf(v[j], v[j], s2);
            }
#pragma unroll
            for (int off = 16; off; off >>= 1) {
                s  += __shfl_xor_sync(0xffffffffu, s, off);
                s2 += __shfl_xor_sync(0xffffffffu, s2, off);
            }
            float mu = s * (1.f / 128.f);
            float var = s2 * (1.f / 128.f) - mu * mu;
            float rs = rsqrtf(fmaxf(var, 0.f) + 1e-5f);
#pragma unroll
            for (int j = 0; j < 4; j++) {
                int c = lane + j * 32;
                float o = (v[j] - mu) * rs * lng[c] + lnbt[c];
                Ys[r * 128 + c] = o > 0.f ? tanhf(o) : 0.f;
            }
        }
        __syncthreads();

        float acc2[16][2];
        {
            float bb0 = __ldg(&b2p[2 * lane]), bb1 = __ldg(&b2p[2 * lane + 1]);
#pragma unroll
            for (int j = 0; j < 16; j++) { acc2[j][0] = bb0; acc2[j][1] = bb1; }
        }
        for (int k4 = 0; k4 < 32; k4++) {
            float2 w[4];
#pragma unroll
            for (int q = 0; q < 4; q++)
                w[q] = *(const float2*)&W2s[(k4 * 4 + q) * 64 + 2 * lane];
#pragma unroll
            for (int j = 0; j < 16; j++) {
                float4 xv = *(const float4*)&Ys[(wid * 16 + j) * 128 + k4 * 4];
                acc2[j][0] = fmaf(xv.x, w[0].x, acc2[j][0]);
                acc2[j][1] = fmaf(xv.x, w[0].y, acc2[j][1]);
                acc2[j][0] = fmaf(xv.y, w[1].x, acc2[j][0]);
                acc2[j][1] = fmaf(xv.y, w[1].y, acc2[j][1]);
                acc2[j][0] = fmaf(xv.z, w[2].x, acc2[j][0]);
                acc2[j][1] = fmaf(xv.z, w[2].y, acc2[j][1]);
                acc2[j][0] = fmaf(xv.w, w[3].x, acc2[j][0]);
                acc2[j][1] = fmaf(xv.w, w[3].y, acc2[j][1]);
            }
        }

        float gg0 = __ldg(&g2p[2 * lane]), gg1 = __ldg(&g2p[2 * lane + 1]);
        float bt0 = __ldg(&bn2p[2 * lane]), bt1 = __ldg(&bn2p[2 * lane + 1]);
        float w30a = W3s[(2 * lane) * 3 + 0], w31a = W3s[(2 * lane) * 3 + 1],
              w32a = W3s[(2 * lane) * 3 + 2];
        float w30b = W3s[(2 * lane + 1) * 3 + 0], w31b = W3s[(2 * lane + 1) * 3 + 1],
              w32b = W3s[(2 * lane + 1) * 3 + 2];
        for (int j = 0; j < 16; j++) {
            float a = acc2[j][0], b = acc2[j][1];
            float s = a + b;
            float s2 = fmaf(a, a, b * b);
#pragma unroll
            for (int off = 16; off; off >>= 1) {
                s  += __shfl_xor_sync(0xffffffffu, s, off);
                s2 += __shfl_xor_sync(0xffffffffu, s2, off);
            }
            float mu = s * (1.f / 64.f);
            float var = s2 * (1.f / 64.f) - mu * mu;
            float rs = rsqrtf(fmaxf(var, 0.f) + 1e-5f);
            float va = (a - mu) * rs * gg0 + bt0;
            float vb = (b - mu) * rs * gg1 + bt1;
            va = va > 0.f ? va : 0.f;
            vb = vb > 0.f ? vb : 0.f;
            float o0 = fmaf(va, w30a, vb * w30b);
            float o1 = fmaf(va, w31a, vb * w31b);
            float o2 = fmaf(va, w32a, vb * w32b);
#pragma unroll
            for (int off = 16; off; off >>= 1) {
                o0 += __shfl_down_sync(0xffffffffu, o0, off);
                o1 += __shfl_down_sync(0xffffffffu, o1, off);
                o2 += __shfl_down_sync(0xffffffffu, o2, off);
            }
            int grow = mBase + wid * 16 + j;
            if (lane == 0 && grow < M) {
                o0 += b3s[0];
                o1 += b3s[1];
                o2 += b3s[2];
                float sq = o0 * o0 + o1 * o1 + o2 * o2;
                g_h4[grow] = make_float4(o0, o1, o2, sq);
            }
        }
    }
}

// ------------------------- per-edge softmax weights (one warp per dst) -------------------------
__device__ __forceinline__ float lrelu02(float x) { return x > 0.f ? x : 0.2f * x; }

__global__ void k_alpha() {
    int gw = (blockIdx.x * blockDim.x + threadIdx.x) >> 5;
    int lane = threadIdx.x & 31;
    if (gw >= NN) return;
    int s0 = g_rowptr[gw], s1 = g_rowptr[gw + 1];
    float ad0 = g_ad[gw * 2], ad1 = g_ad[gw * 2 + 1];
    float m0 = -1e30f, m1 = -1e30f;
    for (int i = s0 + lane; i < s1; i += 32) {
        int s = g_csr[i];
        m0 = fmaxf(m0, lrelu02(g_as[s * 2] + ad0));
        m1 = fmaxf(m1, lrelu02(g_as[s * 2 + 1] + ad1));
    }
#pragma unroll
    for (int off = 16; off; off >>= 1) {
        m0 = fmaxf(m0, __shfl_xor_sync(0xffffffffu, m0, off));
        m1 = fmaxf(m1, __shfl_xor_sync(0xffffffffu, m1, off));
    }
    float z0 = 0.f, z1 = 0.f;
    for (int i = s0 + lane; i < s1; i += 32) {
        int s = g_csr[i];
        float w0 = __expf(lrelu02(g_as[s * 2] + ad0) - m0);
        float w1 = __expf(lrelu02(g_as[s * 2 + 1] + ad1) - m1);
        g_w2[i] = make_float2(w0, w1);
        z0 += w0;
        z1 += w1;
    }
#pragma unroll
    for (int off = 16; off; off >>= 1) {
        z0 += __shfl_xor_sync(0xffffffffu, z0, off);
        z1 += __shfl_xor_sync(0xffffffffu, z1, off);
    }
    if (lane == 0) {
        g_zi[gw * 2]     = 1.f / (z0 + 1e-16f);
        g_zi[gw * 2 + 1] = 1.f / (z1 + 1e-16f);
    }
}

// ------------------------- aggregate (fp16 gather, 16x unrolled) + relu + bf16 split -------------------------
__device__ __forceinline__ void agg_edge4(int i, int head, int t, float4& acc) {
    int sa = g_csr[i], sb = g_csr[i + 1], sc = g_csr[i + 2], sd = g_csr[i + 3];
    float2 wa2 = g_w2[i], wb2 = g_w2[i + 1], wc2 = g_w2[i + 2], wd2 = g_w2[i + 3];
    float wa = head ? wa2.y : wa2.x;
    float wb = head ? wb2.y : wb2.x;
    float wc = head ? wc2.y : wc2.x;
    float wd = head ? wd2.y : wd2.x;
    uint2 ua = *(const uint2*)&g_Hh[(size_t)sa * 512 + t * 4];
    uint2 ub = *(const uint2*)&g_Hh[(size_t)sb * 512 + t * 4];
    uint2 uc = *(const uint2*)&g_Hh[(size_t)sc * 512 + t * 4];
    uint2 ud = *(const uint2*)&g_Hh[(size_t)sd * 512 + t * 4];
    float2 a01 = __half22float2(*(__half2*)&ua.x), a23 = __half22float2(*(__half2*)&ua.y);
    float2 b01 = __half22float2(*(__half2*)&ub.x), b23 = __half22float2(*(__half2*)&ub.y);
    float2 c01 = __half22float2(*(__half2*)&uc.x), c23 = __half22float2(*(__half2*)&uc.y);
    float2 d01 = __half22float2(*(__half2*)&ud.x), d23 = __half22float2(*(__half2*)&ud.y);
    acc.x = fmaf(wa, a01.x, fmaf(wb, b01.x, fmaf(wc, c01.x, fmaf(wd, d01.x, acc.x))));
    acc.y = fmaf(wa, a01.y, fmaf(wb, b01.y, fmaf(wc, c01.y, fmaf(wd, d01.y, acc.y))));
    acc.z = fmaf(wa, a23.x, fmaf(wb, b23.x, fmaf(wc, c23.x, fmaf(wd, d23.x, acc.z))));
    acc.w = fmaf(wa, a23.y, fmaf(wb, b23.y, fmaf(wc, c23.y, fmaf(wd, d23.y, acc.w))));
}

__global__ void k_agg2(const float* __restrict__ bgat) {
    int n = blockIdx.x;
    int t = threadIdx.x;  // 128 threads, 4 channels each
    int head = t >> 6;
    int s0 = g_rowptr[n], s1 = g_rowptr[n + 1];
    float4 acc = make_float4(0.f, 0.f, 0.f, 0.f);
    int i = s0;
    for (; i + 16 <= s1; i += 16) {
        agg_edge4(i, head, t, acc);
        agg_edge4(i + 4, head, t, acc);
        agg_edge4(i + 8, head, t, acc);
        agg_edge4(i + 12, head, t, acc);
    }
    for (; i + 4 <= s1; i += 4) {
        agg_edge4(i, head, t, acc);
    }
    for (; i < s1; i++) {
        int s = g_csr[i];
        float2 w2 = g_w2[i];
        float w = head ? w2.y : w2.x;
        uint2 u = *(const uint2*)&g_Hh[(size_t)s * 512 + t * 4];
        float2 h01 = __half22float2(*(__half2*)&u.x), h23 = __half22float2(*(__half2*)&u.y);
        acc.x = fmaf(w, h01.x, acc.x);
        acc.y = fmaf(w, h01.y, acc.y);
        acc.z = fmaf(w, h23.x, acc.z);
        acc.w = fmaf(w, h23.y, acc.w);
    }
    float zi = g_zi[n * 2 + head];
    float4 b4 = *(const float4*)&bgat[t * 4];
    float4 o;
    o.x = fmaf(acc.x, zi, b4.x);
    o.y = fmaf(acc.y, zi, b4.y);
    o.z = fmaf(acc.z, zi, b4.z);
    o.w = fmaf(acc.w, zi, b4.w);
    o.x = o.x > 0.f ? o.x : 0.f;
    o.y = o.y > 0.f ? o.y : 0.f;
    o.z = o.z > 0.f ? o.z : 0.f;
    o.w = o.w > 0.f ? o.w : 0.f;
    __nv_bfloat16 h0 = __float2bfloat16_rn(o.x), h1 = __float2bfloat16_rn(o.y);
    __nv_bfloat16 h2 = __float2bfloat16_rn(o.z), h3 = __float2bfloat16_rn(o.w);
    float l0 = o.x - __bfloat162float(h0), l1 = o.y - __bfloat162float(h1);
    float l2 = o.z - __bfloat162float(h2), l3 = o.w - __bfloat162float(h3);
    uint32_t hp0 = (((uint32_t)*(uint16_t*)&h1) << 16) | (uint32_t)*(uint16_t*)&h0;
    uint32_t hp1 = (((uint32_t)*(uint16_t*)&h3) << 16) | (uint32_t)*(uint16_t*)&h2;
    ((uint2*)g_Xhi)[n * 128 + t] = make_uint2(hp0, hp1);
    ((uint2*)g_Xlo)[n * 128 + t] = make_uint2(pack_bf2(l0, l1), pack_bf2(l2, l3));
}

// ------------------------- bias + LN + relu epilogue, bf16 split out (layerA) -------------------------
__global__ void k_ln_act256(const float* __restrict__ pre, const float* __restrict__ bias,
                            const float* __restrict__ gam, const float* __restrict__ bet,
                            __nv_bfloat16* __restrict__ oHi, __nv_bfloat16* __restrict__ oLo) {
    int row = blockIdx.x * 8 + (threadIdx.x >> 5);
    int lane = threadIdx.x & 31;
    if (row >= NN) return;
    const float* p = pre + (size_t)row * 256;
    float v[8];
    float s = 0.f, s2 = 0.f;
#pragma unroll
    for (int j = 0; j < 8; j++) {
        int c = lane + j * 32;
        v[j] = p[c] + bias[c];
        s += v[j];
        s2 = fmaf(v[j], v[j], s2);
    }
#pragma unroll
    for (int off = 16; off; off >>= 1) {
        s  += __shfl_xor_sync(0xffffffffu, s, off);
        s2 += __shfl_xor_sync(0xffffffffu, s2, off);
    }
    float mu = s * (1.f / 256.f);
    float var = s2 * (1.f / 256.f) - mu * mu;
    float rs = rsqrtf(fmaxf(var, 0.f) + 1e-5f);
#pragma unroll
    for (int j = 0; j < 8; j++) {
        int c = lane + j * 32;
        float o = (v[j] - mu) * rs * gam[c] + bet[c];
        o = o > 0.f ? o : 0.f;
        __nv_bfloat16 h = __float2bfloat16_rn(o);
        float l = o - __bfloat162float(h);
        oHi[(size_t)row * 256 + c] = h;
        oLo[(size_t)row * 256 + c] = __float2bfloat16_rn(l);
    }
}

// ------------------------- pairwise distance (MUFU.SQRT, streaming stores) -------------------------
__device__ __forceinline__ float pdist(float4 a, float4 b) {
    float dot = fmaf(a.x, b.x, fmaf(a.y, b.y, a.z * b.z));
    float d = fmaf(-2.f, dot, a.w + b.w);
    return fsqrt_ap(fmaxf(d, 0.f));
}

__global__ void k_cdist(float* __restrict__ out) {
    int j4 = blockIdx.x * blockDim.x + threadIdx.x;
    if (j4 >= NN / 4) return;
    int i0 = blockIdx.y * 4;
    float4 bq0 = g_h4[4 * j4 + 0];
    float4 bq1 = g_h4[4 * j4 + 1];
    float4 bq2 = g_h4[4 * j4 + 2];
    float4 bq3 = g_h4[4 * j4 + 3];
#pragma unroll
    for (int r = 0; r < 4; r++) {
        float4 a = g_h4[i0 + r];
        float4 o = make_float4(pdist(a, bq0), pdist(a, bq1), pdist(a, bq2), pdist(a, bq3));
        __stcs((float4*)(out + (size_t)(i0 + r) * NN + 4 * j4), o);
    }
}

// ------------------------- streams -------------------------
static cudaStream_t s_edge = nullptr, s_wts = nullptr;
static cudaEvent_t ev_start = nullptr, ev_edge = nullptr, ev_wts = nullptr, ev_wts2 = nullptr;
struct HxInit {
    HxInit() {
        cudaStreamCreateWithFlags(&s_edge, cudaStreamNonBlocking);
        cudaStreamCreateWithFlags(&s_wts, cudaStreamNonBlocking);
        cudaEventCreateWithFlags(&ev_start, cudaEventDisableTiming);
        cudaEventCreateWithFlags(&ev_edge, cudaEventDisableTiming);
        cudaEventCreateWithFlags(&ev_wts, cudaEventDisableTiming);
        cudaEventCreateWithFlags(&ev_wts2, cudaEventDisableTiming);
    }
};
static HxInit g_hxinit;

// ------------------------- launch -------------------------
extern "C" void kernel_launch(void* const* d_in, const int* in_sizes, int n_in,
                              void* d_out, int out_size) {
    const float* x      = (const float*)d_in[0];
    const void*  ei     = d_in[1];
    const float* W_gat  = (const float*)d_in[2];
    const float* attS   = (const float*)d_in[3];
    const float* attD   = (const float*)d_in[4];
    const float* b_gat  = (const float*)d_in[5];
    const float* Wa     = (const float*)d_in[6];
    const float* ba     = (const float*)d_in[7];
    const float* ga     = (const float*)d_in[8];
    const float* bna    = (const float*)d_in[9];
    const float* W1     = (const float*)d_in[10];
    const float* b1     = (const float*)d_in[11];
    const float* g1     = (const float*)d_in[12];
    const float* bn1    = (const float*)d_in[13];
    const float* W2     = (const float*)d_in[14];
    const float* b2     = (const float*)d_in[15];
    const float* g2     = (const float*)d_in[16];
    const float* bn2    = (const float*)d_in[17];
    const float* W3     = (const float*)d_in[18];
    const float* b3     = (const float*)d_in[19];
    float* out = (float*)d_out;

    int E = in_sizes[1] / 2;
    int tot = E + NN;

    static float* pPre = nullptr;
    static int* pCnt = nullptr;
    static __nv_bfloat16 *pBhi = nullptr, *pBlo = nullptr, *pBhi2 = nullptr, *pBlo2 = nullptr,
                         *pBhiW1 = nullptr, *pBloW1 = nullptr, *pXhi = nullptr, *pXlo = nullptr;
    static bool attrDone = false;
    if (!pPre) {
        cudaGetSymbolAddress((void**)&pPre, g_pre);
        cudaGetSymbolAddress((void**)&pCnt, g_cnt);
        cudaGetSymbolAddress((void**)&pBhi, g_Bhi);
        cudaGetSymbolAddress((void**)&pBlo, g_Blo);
        cudaGetSymbolAddress((void**)&pBhi2, g_Bhi2);
        cudaGetSymbolAddress((void**)&pBlo2, g_Blo2);
        cudaGetSymbolAddress((void**)&pBhiW1, g_BhiW1);
        cudaGetSymbolAddress((void**)&pBloW1, g_BloW1);
        cudaGetSymbolAddress((void**)&pXhi, g_Xhi);
        cudaGetSymbolAddress((void**)&pXlo, g_Xlo);
    }
    if (!attrDone) {
        cudaFuncSetAttribute((const void*)k_gemm_mma<512, 512, 3>,
                             cudaFuncAttributeMaxDynamicSharedMemorySize, 2 * GSTAGE);
        cudaFuncSetAttribute((const void*)k_gemm_mma<512, 256, 0>,
                             cudaFuncAttributeMaxDynamicSharedMemorySize, 2 * GSTAGE);
        cudaFuncSetAttribute((const void*)k_gemm_mma<256, 128, 1>,
                             cudaFuncAttributeMaxDynamicSharedMemorySize, 2 * GSTAGE);
        attrDone = true;
    }

    // fork
    cudaEventRecord(ev_start, 0);
    cudaStreamWaitEvent(s_edge, ev_start, 0);
    cudaStreamWaitEvent(s_wts, ev_start, 0);

    // Issue order chosen so GEMM1 is the 5th kernel launch (ncu capture slot);
    // all dependencies are carried by events, so semantics are unchanged.
    cudaMemsetAsync(pCnt, 0, NN * sizeof(int), s_edge);               // launch 1

    int n4x = NN * 512 / 4;
    k_split<<<(n4x + 255) / 256, 256>>>((const float4*)x, (uint2*)pXhi, (uint2*)pXlo, n4x);  // 2

    k_prepWT<<<512, 256, 0, s_wts>>>(W_gat, 512, 512, pBhi, pBlo);    // 3
    cudaEventRecord(ev_wts, s_wts);

    k_detect<<<1, 1, 0, s_edge>>>(ei);                                // 4

    cudaStreamWaitEvent(0, ev_wts, 0);
    {
        dim3 gg(4, (NN + 127) / 128);                                 // 5: GEMM1 (ncu target)
        k_gemm_mma<512, 512, 3><<<gg, 256, 2 * GSTAGE>>>(
            pXhi, pXlo, pBhi, pBlo, nullptr, NN, nullptr, nullptr, nullptr,
            nullptr, nullptr, nullptr, nullptr, nullptr, nullptr);
    }

    // rest of edge + attention-weight chain (stream E)
    k_convert<<<(tot + 255) / 256, 256, 0, s_edge>>>(ei, E);
    k_scan<<<1, 1024, 0, s_edge>>>();
    k_scatter<<<(tot + 255) / 256, 256, 0, s_edge>>>(tot);
    k_attvec<<<128, 256, 0, s_edge>>>(W_gat, attS, attD);
    k_attdot2<<<(NN * 32 + 255) / 256, 256, 0, s_edge>>>(x);
    k_alpha<<<(NN * 32 + 255) / 256, 256, 0, s_edge>>>();
    cudaEventRecord(ev_edge, s_edge);

    // remaining weight splits (stream W)
    k_prepWT<<<256, 256, 0, s_wts>>>(Wa, 512, 256, pBhi2, pBlo2);
    k_prepWT<<<128, 256, 0, s_wts>>>(W1, 256, 128, pBhiW1, pBloW1);
    cudaEventRecord(ev_wts2, s_wts);

    cudaStreamWaitEvent(0, ev_edge, 0);
    k_agg2<<<NN, 128>>>(b_gat);   // fp16 gather; emits bf16 hi/lo into g_Xhi/g_Xlo

    cudaStreamWaitEvent(0, ev_wts2, 0);
    // layer A: pre = gat @ Wa  -> LN+relu -> hi/lo split
    {
        dim3 gg(2, (NN + 127) / 128);
        k_gemm_mma<512, 256, 0><<<gg, 256, 2 * GSTAGE>>>(
            pXhi, pXlo, pBhi2, pBlo2, pPre, NN, nullptr, nullptr, nullptr,
            nullptr, nullptr, nullptr, nullptr, nullptr, nullptr);
    }
    k_ln_act256<<<(NN + 7) / 8, 256>>>(pPre, ba, ga, bna, pXhi, pXlo);

    // layer 1 GEMM with fully fused tail (LN+tanh -> layer2 -> LN+relu -> layer3 -> g_h4)
    {
        dim3 gg(1, (NN + 127) / 128);
        k_gemm_mma<256, 128, 1><<<gg, 256, 2 * GSTAGE>>>(
            pXhi, pXlo, pBhiW1, pBloW1, nullptr, NN, b1, g1, bn1,
            W2, b2, g2, bn2, W3, b3);
    }

    dim3 gc((NN / 4 + 255) / 256, NN / 4);
    k_cdist<<<gc, 256>>>(out);
}